// round 13
// baseline (speedup 1.0000x reference)
#include <cuda_runtime.h>
#include <cuda_fp16.h>
#include <math.h>
#include <stdint.h>

#define Bc  4
#define Tc  2048
#define Dc  1024
#define Hc  8
#define HDc 128
#define Mc  (Bc*Tc)

// Scratch (fp16)
__device__ __half g_qh[Bc*Tc*Dc];           // [B,H,T,HD], pre-scaled by c*log2e
__device__ __half g_kh[Bc*Tc*Dc];           // [B,H,T,HD]
__device__ __half g_vt[Bc*Tc*Dc];           // [B,H,HD,T]  (V transposed)
__device__ __half g_ch[Bc*Tc*Dc];           // ctx [B,H,T,HD]
__device__ __half g_xh[Bc*Tc*Dc];
__device__ __half g_yh[Bc*Tc*Dc];
__device__ __half g_wh[4][Dc*Dc];

// ---------------------------------------------------------------------------
// helpers
// ---------------------------------------------------------------------------
__device__ __forceinline__ uint32_t smem_u32(const void* p) {
    uint32_t a;
    asm("{ .reg .u64 t; cvta.to.shared.u64 t, %1; cvt.u32.u64 %0, t; }"
        : "=r"(a) : "l"(p));
    return a;
}
__device__ __forceinline__ float ex2(float x) {
    float y;
    asm("ex2.approx.f32 %0, %1;" : "=f"(y) : "f"(x));
    return y;
}
__device__ __forceinline__ uint32_t h2u(float a, float b) {
    __half2 h = __floats2half2_rn(a, b);
    return *(uint32_t*)&h;
}
__device__ __forceinline__ void cp16(uint32_t dst, const void* src) {
    asm volatile("cp.async.cg.shared.global [%0], [%1], 16;" :: "r"(dst), "l"(src));
}
#define CP_COMMIT() asm volatile("cp.async.commit_group;" ::: "memory")
#define CP_WAIT1()  asm volatile("cp.async.wait_group 1;" ::: "memory")
#define CP_WAIT0()  asm volatile("cp.async.wait_group 0;" ::: "memory")

// ldmatrix x4 (b16, non-trans)
__device__ __forceinline__ void ldm4(uint32_t addr, uint32_t* r) {
    asm volatile("ldmatrix.sync.aligned.m8n8.x4.shared.b16 {%0,%1,%2,%3}, [%4];"
                 : "=r"(r[0]), "=r"(r[1]), "=r"(r[2]), "=r"(r[3]) : "r"(addr));
}

// m16n8k16 fp16 MMA, f32 accumulate in place.
__device__ __forceinline__ void mma16(float* d, const uint32_t* a,
                                      uint32_t b0, uint32_t b1) {
    asm volatile(
        "mma.sync.aligned.m16n8k16.row.col.f32.f16.f16.f32 "
        "{%0,%1,%2,%3}, {%4,%5,%6,%7}, {%8,%9}, {%0,%1,%2,%3};"
        : "+f"(d[0]), "+f"(d[1]), "+f"(d[2]), "+f"(d[3])
        : "r"(a[0]), "r"(a[1]), "r"(a[2]), "r"(a[3]), "r"(b0), "r"(b1));
}

#define CSC 0.12751743342f   // (1/sqrt(128)) * log2(e)

// ---------------------------------------------------------------------------
// fp32 -> fp16 converts (2 fused launches)
// ---------------------------------------------------------------------------
__global__ void conv_h2(const float4* __restrict__ a, uint2* __restrict__ oa,
                        const float4* __restrict__ b, uint2* __restrict__ ob,
                        int n4) {
    int i = blockIdx.x * blockDim.x + threadIdx.x;
    const float4* s = blockIdx.y ? b : a;
    uint2* d = blockIdx.y ? ob : oa;
    if (i < n4) {
        float4 v = s[i];
        uint2 o;
        o.x = h2u(v.x, v.y);
        o.y = h2u(v.z, v.w);
        d[i] = o;
    }
}

__global__ void conv_h4(const float4* __restrict__ w0, const float4* __restrict__ w1,
                        const float4* __restrict__ w2, const float4* __restrict__ w3,
                        uint2* __restrict__ o0, int n4) {
    int i = blockIdx.x * blockDim.x + threadIdx.x;
    const float4* s = (blockIdx.y == 0) ? w0 : (blockIdx.y == 1) ? w1
                      : (blockIdx.y == 2) ? w2 : w3;
    uint2* d = o0 + (size_t)blockIdx.y * (Dc * Dc / 4);
    if (i < n4) {
        float4 v = s[i];
        uint2 o;
        o.x = h2u(v.x, v.y);
        o.y = h2u(v.z, v.w);
        d[i] = o;
    }
}

// ---------------------------------------------------------------------------
// Fused Q/K/V projection GEMM (round-9 mainloop; blockIdx.z selects problem).
// z=0: Q = (x Wq^T + bq)*CSC -> g_qh   (scale folded for flash)
// z=1: K = y Wk^T + bk       -> g_kh
// z=2: V = y Wv^T + bv       -> g_vt (V^T layout, smem-staged transpose)
// ---------------------------------------------------------------------------
#define GEMM_SMEM (3*20480)

__global__ __launch_bounds__(256, 2)
void gemm_qkv(const __half* __restrict__ Ax, const __half* __restrict__ Ay,
              const __half* __restrict__ gw,
              const float* __restrict__ bq, const float* __restrict__ bk,
              const float* __restrict__ bv,
              __half* __restrict__ gq, __half* __restrict__ gk,
              __half* __restrict__ gvt)
{
    extern __shared__ __align__(16) char smemc[];
    const uint32_t sb = smem_u32(smemc);

    const int z = blockIdx.z;
    const __half* A    = (z == 0) ? Ax : Ay;
    const __half* Wg   = gw + (size_t)z * Dc * Dc;
    const float*  bias = (z == 0) ? bq : (z == 1) ? bk : bv;
    __half*       outh = (z == 0) ? gq : (z == 1) ? gk : gvt;
    const float   osc  = (z == 0) ? CSC : 1.0f;

    const int tid = threadIdx.x;
    const int wid = tid >> 5, lane = tid & 31;
    const int g = lane >> 2, t = lane & 3;
    const int wm = (wid & 3) * 32, wn = (wid >> 2) * 64;
    const int bn = blockIdx.x * 128, bm = blockIdx.y * 128;

    const int a_row = lane & 15, a_col8 = ((lane >> 4) & 1) * 8;
    const int b_rgrp = (lane >> 4) & 1, b_row = lane & 7;
    const int b_col8 = ((lane >> 3) & 1) * 8;

    auto issue = [&](int stg, int k0) {
        const uint32_t da = sb + (uint32_t)(stg * 20480);
        const uint32_t db = da + 10240u;
#pragma unroll
        for (int it = 0; it < 2; it++) {
            const int idx = tid + it * 256;          // 0..511
            const int row = idx >> 2, s = idx & 3;
            cp16(da + (uint32_t)(row * 40 + s * 8) * 2u,
                 A + (size_t)(bm + row) * Dc + k0 + s * 8);
        }
#pragma unroll
        for (int it = 0; it < 2; it++) {
            const int idx = tid + it * 256;
            const int row = idx >> 2, s = idx & 3;
            cp16(db + (uint32_t)(row * 40 + s * 8) * 2u,
                 Wg + (size_t)(bn + row) * Dc + k0 + s * 8);
        }
        CP_COMMIT();
    };

    float c[2][8][4];
#pragma unroll
    for (int mt = 0; mt < 2; mt++)
#pragma unroll
        for (int nt = 0; nt < 8; nt++)
#pragma unroll
            for (int j = 0; j < 4; j++) c[mt][nt][j] = 0.f;

    issue(0, 0); issue(1, 32);

    for (int i = 0; i < 32; i++) {
        if (i == 31) { CP_WAIT0(); } else { CP_WAIT1(); }
        __syncthreads();
        if (i + 2 < 32) issue((i + 2) % 3, (i + 2) * 32);

        const uint32_t as = sb + (uint32_t)((i % 3) * 20480);
        const uint32_t bs = as + 10240u;

#pragma unroll
        for (int ks = 0; ks < 2; ks++) {
            const int kk = ks * 16;
            uint32_t a[2][4];
#pragma unroll
            for (int mt = 0; mt < 2; mt++)
                ldm4(as + (uint32_t)((wm + mt * 16 + a_row) * 40 + kk + a_col8) * 2u,
                     a[mt]);
#pragma unroll
            for (int j = 0; j < 4; j++) {
                uint32_t br[4];
                ldm4(bs + (uint32_t)((wn + (2 * j + b_rgrp) * 8 + b_row) * 40
                                     + kk + b_col8) * 2u, br);
#pragma unroll
                for (int mt = 0; mt < 2; mt++) {
                    mma16(c[mt][2 * j],     a[mt], br[0], br[1]);
                    mma16(c[mt][2 * j + 1], a[mt], br[2], br[3]);
                }
            }
        }
    }
    __syncthreads();   // protect smem reuse by z==2 epilogue staging

    const int b0i_base = bm >> 11, t0 = bm & 2047;
    const int h = bn >> 7;

    if (z == 2) {
        __half* Ts = (__half*)smemc;          // [128 n][136] halves
#pragma unroll
        for (int mt = 0; mt < 2; mt++) {
            const int r0l = wm + mt * 16 + g, r1l = r0l + 8;
#pragma unroll
            for (int nt = 0; nt < 8; nt++) {
                const int cl = wn + nt * 8 + 2 * t;
                const float bx = __ldg(bias + bn + cl);
                const float by = __ldg(bias + bn + cl + 1);
                Ts[(cl    ) * 136 + r0l] = __float2half_rn(c[mt][nt][0] + bx);
                Ts[(cl + 1) * 136 + r0l] = __float2half_rn(c[mt][nt][1] + by);
                Ts[(cl    ) * 136 + r1l] = __float2half_rn(c[mt][nt][2] + bx);
                Ts[(cl + 1) * 136 + r1l] = __float2half_rn(c[mt][nt][3] + by);
            }
        }
        __syncthreads();
#pragma unroll
        for (int it = 0; it < 8; it++) {
            const int idx = tid + it * 256;          // 0..2047
            const int row = idx >> 4, s = idx & 15;
            const uint4 v = *(const uint4*)&Ts[row * 136 + s * 8];
            *(uint4*)&outh[(((size_t)(b0i_base * Hc + h) * HDc + row)
                            * Tc) + t0 + s * 8] = v;
        }
        return;
    }

#pragma unroll
    for (int mt = 0; mt < 2; mt++) {
        const int r0 = bm + wm + mt * 16 + g;
        const int r1 = r0 + 8;
#pragma unroll
        for (int nt = 0; nt < 8; nt++) {
            const int cl = wn + nt * 8 + 2 * t;
            const int col = bn + cl;
            const float bx = __ldg(bias + col), by = __ldg(bias + col + 1);
            const float v00 = (c[mt][nt][0] + bx) * osc;
            const float v01 = (c[mt][nt][1] + by) * osc;
            const float v10 = (c[mt][nt][2] + bx) * osc;
            const float v11 = (c[mt][nt][3] + by) * osc;
            const int b0i = r0 >> 11, t0i = r0 & 2047;
            const int b1i = r1 >> 11, t1i = r1 & 2047;
            *(uint32_t*)&outh[(((size_t)(b0i * Hc + h) * Tc + t0i) * HDc) + cl]
                = h2u(v00, v01);
            *(uint32_t*)&outh[(((size_t)(b1i * Hc + h) * Tc + t1i) * HDc) + cl]
                = h2u(v10, v11);
        }
    }
}

// ---------------------------------------------------------------------------
// Output projection GEMM (round-10 MODE1 config): out = ctx Wo^T + bo (fp32)
// CTA: 128 threads (4 warps), tile 64(M) x 128(N); warp 32x64; 4 CTAs/SM.
// 1024 CTAs -> 3.46 waves (better tail than 512/1.73).
// ---------------------------------------------------------------------------
#define GOUT_SMEM (3*15360)

__global__ __launch_bounds__(128, 4)
void gemm_out(const __half* __restrict__ A, const __half* __restrict__ Wg,
              const float* __restrict__ bias, float* __restrict__ outf)
{
    extern __shared__ __align__(16) char smemc[];
    const uint32_t sb = smem_u32(smemc);

    const int tid = threadIdx.x;
    const int wid = tid >> 5, lane = tid & 31;
    const int g = lane >> 2, t = lane & 3;
    const int wm = (wid & 1) * 32, wn = (wid >> 1) * 64;
    const int bn = blockIdx.x * 128, bm = blockIdx.y * 64;

    const int a_row = lane & 15, a_col8 = ((lane >> 4) & 1) * 8;
    const int b_rgrp = (lane >> 4) & 1, b_row = lane & 7;
    const int b_col8 = ((lane >> 3) & 1) * 8;

    auto issue = [&](int stg, int k0) {
        const uint32_t da = sb + (uint32_t)(stg * 15360);
        const uint32_t db = da + 5120u;
#pragma unroll
        for (int it = 0; it < 2; it++) {
            const int idx = tid + it * 128;          // 0..255
            const int row = idx >> 2, s = idx & 3;
            const int m = bm + row, b = m >> 11, tt = m & 2047;
            const int kg = k0 + s * 8;
            const int h = kg >> 7, d = kg & 127;
            cp16(da + (uint32_t)(row * 40 + s * 8) * 2u,
                 A + (((size_t)(b * Hc + h) * Tc + tt) * HDc + d));
        }
#pragma unroll
        for (int it = 0; it < 4; it++) {
            const int idx = tid + it * 128;          // 0..511
            const int row = idx >> 2, s = idx & 3;
            cp16(db + (uint32_t)(row * 40 + s * 8) * 2u,
                 Wg + (size_t)(bn + row) * Dc + k0 + s * 8);
        }
        CP_COMMIT();
    };

    float c[2][8][4];
#pragma unroll
    for (int mt = 0; mt < 2; mt++)
#pragma unroll
        for (int nt = 0; nt < 8; nt++)
#pragma unroll
            for (int j = 0; j < 4; j++) c[mt][nt][j] = 0.f;

    issue(0, 0); issue(1, 32);

    for (int i = 0; i < 32; i++) {
        if (i == 31) { CP_WAIT0(); } else { CP_WAIT1(); }
        __syncthreads();
        if (i + 2 < 32) issue((i + 2) % 3, (i + 2) * 32);

        const uint32_t as = sb + (uint32_t)((i % 3) * 15360);
        const uint32_t bs = as + 5120u;

#pragma unroll
        for (int ks = 0; ks < 2; ks++) {
            const int kk = ks * 16;
            uint32_t a[2][4];
#pragma unroll
            for (int mt = 0; mt < 2; mt++)
                ldm4(as + (uint32_t)((wm + mt * 16 + a_row) * 40 + kk + a_col8) * 2u,
                     a[mt]);
#pragma unroll
            for (int j = 0; j < 4; j++) {
                uint32_t br[4];
                ldm4(bs + (uint32_t)((wn + (2 * j + b_rgrp) * 8 + b_row) * 40
                                     + kk + b_col8) * 2u, br);
#pragma unroll
                for (int mt = 0; mt < 2; mt++) {
                    mma16(c[mt][2 * j],     a[mt], br[0], br[1]);
                    mma16(c[mt][2 * j + 1], a[mt], br[2], br[3]);
                }
            }
        }
    }

#pragma unroll
    for (int mt = 0; mt < 2; mt++) {
        const int r0 = bm + wm + mt * 16 + g;
        const int r1 = r0 + 8;
#pragma unroll
        for (int nt = 0; nt < 8; nt++) {
            const int cl = wn + nt * 8 + 2 * t;
            const int col = bn + cl;
            const float bx = __ldg(bias + col), by = __ldg(bias + col + 1);
            *(float2*)&outf[(size_t)r0 * Dc + col]
                = make_float2(c[mt][nt][0] + bx, c[mt][nt][1] + by);
            *(float2*)&outf[(size_t)r1 * Dc + col]
                = make_float2(c[mt][nt][2] + bx, c[mt][nt][3] + by);
        }
    }
}

// ---------------------------------------------------------------------------
// Flash attention fp16 (round-9 structure; Q pre-scaled; diagonal culling)
// ---------------------------------------------------------------------------
#define FLASH_SMEM 80896
#define HK0  0
#define HK1  8704
#define HV0  17408
#define HV1  26624
#define HPS  35840

__global__ __launch_bounds__(128, 2)
void flash_attn()
{
    extern __shared__ __align__(16) __half fsm[];
    const uint32_t sb = smem_u32(fsm);

    const int bh  = blockIdx.y;
    const int qt  = gridDim.x - 1 - blockIdx.x;    // longest blocks first
    const int qb  = qt * 64;
    const int tid = threadIdx.x;
    const int wid = tid >> 5, lane = tid & 31;
    const int g = lane >> 2, t = lane & 3;
    const int wq = wid * 16;

    const int a_row = lane & 15, a_col8 = ((lane >> 4) & 1) * 8;
    const int b_rgrp = (lane >> 4) & 1, b_row = lane & 7;
    const int b_col8 = ((lane >> 3) & 1) * 8;

    const __half* Qg  = g_qh + (size_t)bh * Tc * HDc;
    const __half* Kg  = g_kh + (size_t)bh * Tc * HDc;
    const __half* Vtg = g_vt + (size_t)bh * HDc * Tc;
    __half*       Og  = g_ch + (size_t)bh * Tc * HDc;

    __half* Ps = fsm + HPS;
    const uint32_t psb = sb + HPS * 2u;

    // Q fragments (pre-scaled by CSC at projection), held all loop
    uint32_t qf[8][4];
    {
        const int r0 = qb + wq + g, r1 = r0 + 8;
#pragma unroll
        for (int ds = 0; ds < 8; ds++) {
            qf[ds][0] = *(const uint32_t*)&Qg[(size_t)r0 * HDc + ds * 16 + 2 * t];
            qf[ds][1] = *(const uint32_t*)&Qg[(size_t)r1 * HDc + ds * 16 + 2 * t];
            qf[ds][2] = *(const uint32_t*)&Qg[(size_t)r0 * HDc + ds * 16 + 8 + 2 * t];
            qf[ds][3] = *(const uint32_t*)&Qg[(size_t)r1 * HDc + ds * 16 + 8 + 2 * t];
        }
    }

    float o[16][4];
#pragma unroll
    for (int nt = 0; nt < 16; nt++)
#pragma unroll
        for (int j = 0; j < 4; j++) o[nt][j] = 0.f;

    float m0 = -1e30f, m1 = -1e30f, l0 = 0.f, l1 = 0.f;
    const int ktmax = qt;

    auto issue_kv = [&](int buf, int kt) {
        const int kb = kt * 64;
        const uint32_t kd = sb + (buf ? HK1 : HK0) * 2u;
        const uint32_t vd = sb + (buf ? HV1 : HV0) * 2u;
#pragma unroll
        for (int it = 0; it < 8; it++) {
            const int idx = tid + it * 128;          // 0..1023
            const int c = idx >> 4, s = idx & 15;
            cp16(kd + (uint32_t)(c * 136 + s * 8) * 2u,
                 Kg + (size_t)(kb + c) * HDc + s * 8);
        }
#pragma unroll
        for (int it = 0; it < 8; it++) {
            const int idx = tid + it * 128;          // 0..1023
            const int d = idx >> 3, s = idx & 7;
            cp16(vd + (uint32_t)(d * 72 + s * 8) * 2u,
                 Vtg + (size_t)d * Tc + kb + s * 8);
        }
        CP_COMMIT();
    };

    issue_kv(0, 0);

    for (int kt = 0; kt <= ktmax; kt++) {
        const int cur = kt & 1;
        CP_WAIT0();
        __syncthreads();
        if (kt < ktmax) issue_kv(1 - cur, kt + 1);

        const uint32_t ks_b = sb + (cur ? HK1 : HK0) * 2u;
        const uint32_t vs_b = sb + (cur ? HV1 : HV0) * 2u;
        const int kb = kt * 64;

        const bool needm = (kt == qt);
        const int jmax = needm ? wid : 3;   // diagonal culling: blocks j>wid fully masked

        // S = Q K^T : warp 16q x 64c (culled on diagonal)
        float s[8][4];
#pragma unroll
        for (int nt = 0; nt < 8; nt++)
#pragma unroll
            for (int j = 0; j < 4; j++) s[nt][j] = 0.f;

#pragma unroll
        for (int ds = 0; ds < 8; ds++) {
#pragma unroll 4
            for (int j = 0; j <= jmax; j++) {
                uint32_t br[4];
                ldm4(ks_b + (uint32_t)(((2 * j + b_rgrp) * 8 + b_row) * 136
                                       + ds * 16 + b_col8) * 2u, br);
                mma16(s[2 * j],     qf[ds], br[0], br[1]);
                mma16(s[2 * j + 1], qf[ds], br[2], br[3]);
            }
        }

        // causal mask (diagonal tile only); scale already folded into Q
        const int qr0 = qb + wq + g, qr1 = qr0 + 8;
        if (needm) {
#pragma unroll
            for (int nt = 0; nt < 8; nt++) {
                const int c0 = kb + nt * 8 + 2 * t;
                if (c0     > qr0) s[nt][0] = -1e30f;
                if (c0 + 1 > qr0) s[nt][1] = -1e30f;
                if (c0     > qr1) s[nt][2] = -1e30f;
                if (c0 + 1 > qr1) s[nt][3] = -1e30f;
            }
        }

        // online softmax (log2 domain)
        float mx0 = -1e30f, mx1 = -1e30f;
#pragma unroll
        for (int nt = 0; nt < 8; nt++) {
            mx0 = fmaxf(mx0, fmaxf(s[nt][0], s[nt][1]));
            mx1 = fmaxf(mx1, fmaxf(s[nt][2], s[nt][3]));
        }
        mx0 = fmaxf(mx0, __shfl_xor_sync(0xffffffffu, mx0, 1));
        mx0 = fmaxf(mx0, __shfl_xor_sync(0xffffffffu, mx0, 2));
        mx1 = fmaxf(mx1, __shfl_xor_sync(0xffffffffu, mx1, 1));
        mx1 = fmaxf(mx1, __shfl_xor_sync(0xffffffffu, mx1, 2));

        const float mn0 = fmaxf(m0, mx0), mn1 = fmaxf(m1, mx1);
        const float a0 = ex2(m0 - mn0), a1 = ex2(m1 - mn1);

        float ls0 = 0.f, ls1 = 0.f;
#pragma unroll
        for (int nt = 0; nt < 8; nt++) {
            const float p0 = ex2(s[nt][0] - mn0);
            const float p1 = ex2(s[nt][1] - mn0);
            const float p2 = ex2(s[nt][2] - mn1);
            const float p3 = ex2(s[nt][3] - mn1);
            ls0 += p0 + p1; ls1 += p2 + p3;
            *(uint32_t*)&Ps[(wq + g) * 72 + nt * 8 + 2 * t]     = h2u(p0, p1);
            *(uint32_t*)&Ps[(wq + g + 8) * 72 + nt * 8 + 2 * t] = h2u(p2, p3);
        }
        ls0 += __shfl_xor_sync(0xffffffffu, ls0, 1);
        ls0 += __shfl_xor_sync(0xffffffffu, ls0, 2);
        ls1 += __shfl_xor_sync(0xffffffffu, ls1, 1);
        ls1 += __shfl_xor_sync(0xffffffffu, ls1, 2);
        l0 = l0 * a0 + ls0;
        l1 = l1 * a1 + ls1;
        m0 = mn0; m1 = mn1;

#pragma unroll
        for (int nt = 0; nt < 16; nt++) {
            o[nt][0] *= a0; o[nt][1] *= a0;
            o[nt][2] *= a1; o[nt][3] *= a1;
        }
        __syncwarp();    // Ps stores (cross-lane) visible to ldmatrix

        // O += P V : warp 16q x 128d (P chunks > wid are all-zero on diagonal)
#pragma unroll 4
        for (int ks = 0; ks <= jmax; ks++) {
            uint32_t pa[4];
            ldm4(psb + (uint32_t)((wq + a_row) * 72 + ks * 16 + a_col8) * 2u,
                 pa);
#pragma unroll
            for (int j = 0; j < 8; j++) {
                uint32_t vb[4];
                ldm4(vs_b + (uint32_t)(((2 * j + b_rgrp) * 8 + b_row) * 72
                                       + ks * 16 + b_col8) * 2u, vb);
                mma16(o[2 * j],     pa, vb[0], vb[1]);
                mma16(o[2 * j + 1], pa, vb[2], vb[3]);
            }
        }
    }

    // epilogue
    const float il0 = 1.f / l0, il1 = 1.f / l1;
    const int r0 = qb + wq + g, r1 = r0 + 8;
#pragma unroll
    for (int nt = 0; nt < 16; nt++) {
        const int c = nt * 8 + 2 * t;
        *(uint32_t*)&Og[(size_t)r0 * HDc + c] = h2u(o[nt][0] * il0, o[nt][1] * il0);
        *(uint32_t*)&Og[(size_t)r1 * HDc + c] = h2u(o[nt][2] * il1, o[nt][3] * il1);
    }
}

// ---------------------------------------------------------------------------
extern "C" void kernel_launch(void* const* d_in, const int* in_sizes, int n_in,
                              void* d_out, int out_size)
{
    const float* x  = (const float*)d_in[0];
    const float* y  = (const float*)d_in[1];
    const float* Wq = (const float*)d_in[2];
    const float* bq = (const float*)d_in[3];
    const float* Wk = (const float*)d_in[4];
    const float* bk = (const float*)d_in[5];
    const float* Wv = (const float*)d_in[6];
    const float* bv = (const float*)d_in[7];
    const float* Wo = (const float*)d_in[8];
    const float* bo = (const float*)d_in[9];
    float* out = (float*)d_out;

    cudaFuncSetAttribute(flash_attn,
                         cudaFuncAttributeMaxDynamicSharedMemorySize, FLASH_SMEM);
    cudaFuncSetAttribute(gemm_qkv,
                         cudaFuncAttributeMaxDynamicSharedMemorySize, GEMM_SMEM);
    cudaFuncSetAttribute(gemm_out,
                         cudaFuncAttributeMaxDynamicSharedMemorySize, GOUT_SMEM);

    __half* gx; cudaGetSymbolAddress((void**)&gx, g_xh);
    __half* gy; cudaGetSymbolAddress((void**)&gy, g_yh);
    __half* gw; cudaGetSymbolAddress((void**)&gw, g_wh);
    __half* gq; cudaGetSymbolAddress((void**)&gq, g_qh);
    __half* gk; cudaGetSymbolAddress((void**)&gk, g_kh);
    __half* gvt; cudaGetSymbolAddress((void**)&gvt, g_vt);
    __half* gc; cudaGetSymbolAddress((void**)&gc, g_ch);

    // 1. convert inputs + weights to fp16
    const int nXY4 = (Mc * Dc) / 4;
    const int nW4  = (Dc * Dc) / 4;
    conv_h2<<<dim3((nXY4 + 255)/256, 2), 256>>>(
        (const float4*)x, (uint2*)gx, (const float4*)y, (uint2*)gy, nXY4);
    conv_h4<<<dim3((nW4 + 255)/256, 4), 256>>>(
        (const float4*)Wq, (const float4*)Wk, (const float4*)Wv,
        (const float4*)Wo, (uint2*)gw, nW4);

    // 2. fused Q/K/V projections (single launch, 1536 CTAs)
    dim3 gblk(256);
    dim3 qkvgrid(Dc/128, Mc/128, 3);   // (8, 64, 3)
    gemm_qkv<<<qkvgrid, gblk, GEMM_SMEM>>>(gx, gy, gw, bq, bk, bv,
                                           gq, gk, gvt);

    // 3. attention
    dim3 fgrid(Tc/64, Bc*Hc);     // (32, 32) = 1024 CTAs
    flash_attn<<<fgrid, dim3(128), FLASH_SMEM>>>();

    // 4. output projection (BM=64, 1024 CTAs, better tail)
    dim3 ogrid(Dc/128, Mc/64);    // (8, 128)
    gemm_out<<<ogrid, dim3(128), GOUT_SMEM>>>(gc, gw + 3*Dc*Dc, bo, out);
}

// round 14
// speedup vs baseline: 1.5776x; 1.5776x over previous
#include <cuda_runtime.h>
#include <cuda_fp16.h>
#include <math.h>
#include <stdint.h>

#define Bc  4
#define Tc  2048
#define Dc  1024
#define Hc  8
#define HDc 128
#define Mc  (Bc*Tc)

// Scratch (fp16)
__device__ __half g_qh[Bc*Tc*Dc];           // [B,H,T,HD], pre-scaled by c*log2e
__device__ __half g_kh[Bc*Tc*Dc];           // [B,H,T,HD]
__device__ __half g_vt[Bc*Tc*Dc];           // [B,H,HD,T]  (V transposed)
__device__ __half g_ch[Bc*Tc*Dc];           // ctx [B,H,T,HD]
__device__ __half g_xh[Bc*Tc*Dc];
__device__ __half g_yh[Bc*Tc*Dc];
__device__ __half g_wh[4][Dc*Dc];

// ---------------------------------------------------------------------------
// helpers
// ---------------------------------------------------------------------------
__device__ __forceinline__ uint32_t smem_u32(const void* p) {
    uint32_t a;
    asm("{ .reg .u64 t; cvta.to.shared.u64 t, %1; cvt.u32.u64 %0, t; }"
        : "=r"(a) : "l"(p));
    return a;
}
__device__ __forceinline__ float ex2(float x) {
    float y;
    asm("ex2.approx.f32 %0, %1;" : "=f"(y) : "f"(x));
    return y;
}
__device__ __forceinline__ uint32_t h2u(float a, float b) {
    __half2 h = __floats2half2_rn(a, b);
    return *(uint32_t*)&h;
}
__device__ __forceinline__ void cp16(uint32_t dst, const void* src) {
    asm volatile("cp.async.cg.shared.global [%0], [%1], 16;" :: "r"(dst), "l"(src));
}
#define CP_COMMIT() asm volatile("cp.async.commit_group;" ::: "memory")
#define CP_WAIT1()  asm volatile("cp.async.wait_group 1;" ::: "memory")
#define CP_WAIT0()  asm volatile("cp.async.wait_group 0;" ::: "memory")

// ldmatrix x4 (b16, non-trans)
__device__ __forceinline__ void ldm4(uint32_t addr, uint32_t* r) {
    asm volatile("ldmatrix.sync.aligned.m8n8.x4.shared.b16 {%0,%1,%2,%3}, [%4];"
                 : "=r"(r[0]), "=r"(r[1]), "=r"(r[2]), "=r"(r[3]) : "r"(addr));
}

// m16n8k16 fp16 MMA, f32 accumulate in place.
__device__ __forceinline__ void mma16(float* d, const uint32_t* a,
                                      uint32_t b0, uint32_t b1) {
    asm volatile(
        "mma.sync.aligned.m16n8k16.row.col.f32.f16.f16.f32 "
        "{%0,%1,%2,%3}, {%4,%5,%6,%7}, {%8,%9}, {%0,%1,%2,%3};"
        : "+f"(d[0]), "+f"(d[1]), "+f"(d[2]), "+f"(d[3])
        : "r"(a[0]), "r"(a[1]), "r"(a[2]), "r"(a[3]), "r"(b0), "r"(b1));
}

#define CSC 0.12751743342f   // (1/sqrt(128)) * log2(e)

// ---------------------------------------------------------------------------
// fp32 -> fp16 converts (2 fused launches)
// ---------------------------------------------------------------------------
__global__ void conv_h2(const float4* __restrict__ a, uint2* __restrict__ oa,
                        const float4* __restrict__ b, uint2* __restrict__ ob,
                        int n4) {
    int i = blockIdx.x * blockDim.x + threadIdx.x;
    const float4* s = blockIdx.y ? b : a;
    uint2* d = blockIdx.y ? ob : oa;
    if (i < n4) {
        float4 v = s[i];
        uint2 o;
        o.x = h2u(v.x, v.y);
        o.y = h2u(v.z, v.w);
        d[i] = o;
    }
}

__global__ void conv_h4(const float4* __restrict__ w0, const float4* __restrict__ w1,
                        const float4* __restrict__ w2, const float4* __restrict__ w3,
                        uint2* __restrict__ o0, int n4) {
    int i = blockIdx.x * blockDim.x + threadIdx.x;
    const float4* s = (blockIdx.y == 0) ? w0 : (blockIdx.y == 1) ? w1
                      : (blockIdx.y == 2) ? w2 : w3;
    uint2* d = o0 + (size_t)blockIdx.y * (Dc * Dc / 4);
    if (i < n4) {
        float4 v = s[i];
        uint2 o;
        o.x = h2u(v.x, v.y);
        o.y = h2u(v.z, v.w);
        d[i] = o;
    }
}

// ---------------------------------------------------------------------------
// Fused Q/K/V projection GEMM (blockIdx.z selects problem).
// z=0: Q = (x Wq^T + bq)*CSC -> g_qh   (scale folded for flash)
// z=1: K = y Wk^T + bk       -> g_kh
// z=2: V = y Wv^T + bv       -> g_vt (V^T layout, smem-staged transpose)
// ---------------------------------------------------------------------------
#define GEMM_SMEM (3*20480)

__global__ __launch_bounds__(256, 2)
void gemm_qkv(const __half* __restrict__ Ax, const __half* __restrict__ Ay,
              const __half* __restrict__ gw,
              const float* __restrict__ bq, const float* __restrict__ bk,
              const float* __restrict__ bv,
              __half* __restrict__ gq, __half* __restrict__ gk,
              __half* __restrict__ gvt)
{
    extern __shared__ __align__(16) char smemc[];
    const uint32_t sb = smem_u32(smemc);

    const int z = blockIdx.z;
    const __half* A    = (z == 0) ? Ax : Ay;
    const __half* Wg   = gw + (size_t)z * Dc * Dc;
    const float*  bias = (z == 0) ? bq : (z == 1) ? bk : bv;
    __half*       outh = (z == 0) ? gq : (z == 1) ? gk : gvt;
    const float   osc  = (z == 0) ? CSC : 1.0f;

    const int tid = threadIdx.x;
    const int wid = tid >> 5, lane = tid & 31;
    const int g = lane >> 2, t = lane & 3;
    const int wm = (wid & 3) * 32, wn = (wid >> 2) * 64;
    const int bn = blockIdx.x * 128, bm = blockIdx.y * 128;

    const int a_row = lane & 15, a_col8 = ((lane >> 4) & 1) * 8;
    const int b_rgrp = (lane >> 4) & 1, b_row = lane & 7;
    const int b_col8 = ((lane >> 3) & 1) * 8;

    auto issue = [&](int stg, int k0) {
        const uint32_t da = sb + (uint32_t)(stg * 20480);
        const uint32_t db = da + 10240u;
#pragma unroll
        for (int it = 0; it < 2; it++) {
            const int idx = tid + it * 256;          // 0..511
            const int row = idx >> 2, s = idx & 3;
            cp16(da + (uint32_t)(row * 40 + s * 8) * 2u,
                 A + (size_t)(bm + row) * Dc + k0 + s * 8);
        }
#pragma unroll
        for (int it = 0; it < 2; it++) {
            const int idx = tid + it * 256;
            const int row = idx >> 2, s = idx & 3;
            cp16(db + (uint32_t)(row * 40 + s * 8) * 2u,
                 Wg + (size_t)(bn + row) * Dc + k0 + s * 8);
        }
        CP_COMMIT();
    };

    float c[2][8][4];
#pragma unroll
    for (int mt = 0; mt < 2; mt++)
#pragma unroll
        for (int nt = 0; nt < 8; nt++)
#pragma unroll
            for (int j = 0; j < 4; j++) c[mt][nt][j] = 0.f;

    issue(0, 0); issue(1, 32);

    for (int i = 0; i < 32; i++) {
        if (i == 31) { CP_WAIT0(); } else { CP_WAIT1(); }
        __syncthreads();
        if (i + 2 < 32) issue((i + 2) % 3, (i + 2) * 32);

        const uint32_t as = sb + (uint32_t)((i % 3) * 20480);
        const uint32_t bs = as + 10240u;

#pragma unroll
        for (int ks = 0; ks < 2; ks++) {
            const int kk = ks * 16;
            uint32_t a[2][4];
#pragma unroll
            for (int mt = 0; mt < 2; mt++)
                ldm4(as + (uint32_t)((wm + mt * 16 + a_row) * 40 + kk + a_col8) * 2u,
                     a[mt]);
#pragma unroll
            for (int j = 0; j < 4; j++) {
                uint32_t br[4];
                ldm4(bs + (uint32_t)((wn + (2 * j + b_rgrp) * 8 + b_row) * 40
                                     + kk + b_col8) * 2u, br);
#pragma unroll
                for (int mt = 0; mt < 2; mt++) {
                    mma16(c[mt][2 * j],     a[mt], br[0], br[1]);
                    mma16(c[mt][2 * j + 1], a[mt], br[2], br[3]);
                }
            }
        }
    }
    __syncthreads();   // protect smem reuse by z==2 epilogue staging

    const int b0i_base = bm >> 11, t0 = bm & 2047;
    const int h = bn >> 7;

    if (z == 2) {
        __half* Ts = (__half*)smemc;          // [128 n][136] halves
#pragma unroll
        for (int mt = 0; mt < 2; mt++) {
            const int r0l = wm + mt * 16 + g, r1l = r0l + 8;
#pragma unroll
            for (int nt = 0; nt < 8; nt++) {
                const int cl = wn + nt * 8 + 2 * t;
                const float bx = __ldg(bias + bn + cl);
                const float by = __ldg(bias + bn + cl + 1);
                Ts[(cl    ) * 136 + r0l] = __float2half_rn(c[mt][nt][0] + bx);
                Ts[(cl + 1) * 136 + r0l] = __float2half_rn(c[mt][nt][1] + by);
                Ts[(cl    ) * 136 + r1l] = __float2half_rn(c[mt][nt][2] + bx);
                Ts[(cl + 1) * 136 + r1l] = __float2half_rn(c[mt][nt][3] + by);
            }
        }
        __syncthreads();
#pragma unroll
        for (int it = 0; it < 8; it++) {
            const int idx = tid + it * 256;          // 0..2047
            const int row = idx >> 4, s = idx & 15;
            const uint4 v = *(const uint4*)&Ts[row * 136 + s * 8];
            *(uint4*)&outh[(((size_t)(b0i_base * Hc + h) * HDc + row)
                            * Tc) + t0 + s * 8] = v;
        }
        return;
    }

#pragma unroll
    for (int mt = 0; mt < 2; mt++) {
        const int r0 = bm + wm + mt * 16 + g;
        const int r1 = r0 + 8;
#pragma unroll
        for (int nt = 0; nt < 8; nt++) {
            const int cl = wn + nt * 8 + 2 * t;
            const int col = bn + cl;
            const float bx = __ldg(bias + col), by = __ldg(bias + col + 1);
            const float v00 = (c[mt][nt][0] + bx) * osc;
            const float v01 = (c[mt][nt][1] + by) * osc;
            const float v10 = (c[mt][nt][2] + bx) * osc;
            const float v11 = (c[mt][nt][3] + by) * osc;
            const int b0i = r0 >> 11, t0i = r0 & 2047;
            const int b1i = r1 >> 11, t1i = r1 & 2047;
            *(uint32_t*)&outh[(((size_t)(b0i * Hc + h) * Tc + t0i) * HDc) + cl]
                = h2u(v00, v01);
            *(uint32_t*)&outh[(((size_t)(b1i * Hc + h) * Tc + t1i) * HDc) + cl]
                = h2u(v10, v11);
        }
    }
}

// ---------------------------------------------------------------------------
// Output projection GEMM: out = ctx Wo^T + bo (fp32)
// CTA: 128 threads (4 warps), tile 64(M) x 128(N); warp 32x64; 4 CTAs/SM.
// ---------------------------------------------------------------------------
#define GOUT_SMEM (3*15360)

__global__ __launch_bounds__(128, 4)
void gemm_out(const __half* __restrict__ A, const __half* __restrict__ Wg,
              const float* __restrict__ bias, float* __restrict__ outf)
{
    extern __shared__ __align__(16) char smemc[];
    const uint32_t sb = smem_u32(smemc);

    const int tid = threadIdx.x;
    const int wid = tid >> 5, lane = tid & 31;
    const int g = lane >> 2, t = lane & 3;
    const int wm = (wid & 1) * 32, wn = (wid >> 1) * 64;
    const int bn = blockIdx.x * 128, bm = blockIdx.y * 64;

    const int a_row = lane & 15, a_col8 = ((lane >> 4) & 1) * 8;
    const int b_rgrp = (lane >> 4) & 1, b_row = lane & 7;
    const int b_col8 = ((lane >> 3) & 1) * 8;

    auto issue = [&](int stg, int k0) {
        const uint32_t da = sb + (uint32_t)(stg * 15360);
        const uint32_t db = da + 5120u;
#pragma unroll
        for (int it = 0; it < 2; it++) {
            const int idx = tid + it * 128;          // 0..255
            const int row = idx >> 2, s = idx & 3;
            const int m = bm + row, b = m >> 11, tt = m & 2047;
            const int kg = k0 + s * 8;
            const int h = kg >> 7, d = kg & 127;
            cp16(da + (uint32_t)(row * 40 + s * 8) * 2u,
                 A + (((size_t)(b * Hc + h) * Tc + tt) * HDc + d));
        }
#pragma unroll
        for (int it = 0; it < 4; it++) {
            const int idx = tid + it * 128;          // 0..511
            const int row = idx >> 2, s = idx & 3;
            cp16(db + (uint32_t)(row * 40 + s * 8) * 2u,
                 Wg + (size_t)(bn + row) * Dc + k0 + s * 8);
        }
        CP_COMMIT();
    };

    float c[2][8][4];
#pragma unroll
    for (int mt = 0; mt < 2; mt++)
#pragma unroll
        for (int nt = 0; nt < 8; nt++)
#pragma unroll
            for (int j = 0; j < 4; j++) c[mt][nt][j] = 0.f;

    issue(0, 0); issue(1, 32);

    for (int i = 0; i < 32; i++) {
        if (i == 31) { CP_WAIT0(); } else { CP_WAIT1(); }
        __syncthreads();
        if (i + 2 < 32) issue((i + 2) % 3, (i + 2) * 32);

        const uint32_t as = sb + (uint32_t)((i % 3) * 15360);
        const uint32_t bs = as + 5120u;

#pragma unroll
        for (int ks = 0; ks < 2; ks++) {
            const int kk = ks * 16;
            uint32_t a[2][4];
#pragma unroll
            for (int mt = 0; mt < 2; mt++)
                ldm4(as + (uint32_t)((wm + mt * 16 + a_row) * 40 + kk + a_col8) * 2u,
                     a[mt]);
#pragma unroll
            for (int j = 0; j < 4; j++) {
                uint32_t br[4];
                ldm4(bs + (uint32_t)((wn + (2 * j + b_rgrp) * 8 + b_row) * 40
                                     + kk + b_col8) * 2u, br);
#pragma unroll
                for (int mt = 0; mt < 2; mt++) {
                    mma16(c[mt][2 * j],     a[mt], br[0], br[1]);
                    mma16(c[mt][2 * j + 1], a[mt], br[2], br[3]);
                }
            }
        }
    }

#pragma unroll
    for (int mt = 0; mt < 2; mt++) {
        const int r0 = bm + wm + mt * 16 + g;
        const int r1 = r0 + 8;
#pragma unroll
        for (int nt = 0; nt < 8; nt++) {
            const int cl = wn + nt * 8 + 2 * t;
            const int col = bn + cl;
            const float bx = __ldg(bias + col), by = __ldg(bias + col + 1);
            *(float2*)&outf[(size_t)r0 * Dc + col]
                = make_float2(c[mt][nt][0] + bx, c[mt][nt][1] + by);
            *(float2*)&outf[(size_t)r1 * Dc + col]
                = make_float2(c[mt][nt][2] + bx, c[mt][nt][3] + by);
        }
    }
}

// ---------------------------------------------------------------------------
// Flash attention fp16: round-12 structure; Q pre-scaled; diagonal culling
// with FULLY-UNROLLED loops + runtime guards (no dynamic indexing -> no spill)
// ---------------------------------------------------------------------------
#define FLASH_SMEM 80896
#define HK0  0
#define HK1  8704
#define HV0  17408
#define HV1  26624
#define HPS  35840

__global__ __launch_bounds__(128, 2)
void flash_attn()
{
    extern __shared__ __align__(16) __half fsm[];
    const uint32_t sb = smem_u32(fsm);

    const int bh  = blockIdx.y;
    const int qt  = gridDim.x - 1 - blockIdx.x;    // longest blocks first
    const int qb  = qt * 64;
    const int tid = threadIdx.x;
    const int wid = tid >> 5, lane = tid & 31;
    const int g = lane >> 2, t = lane & 3;
    const int wq = wid * 16;

    const int a_row = lane & 15, a_col8 = ((lane >> 4) & 1) * 8;
    const int b_rgrp = (lane >> 4) & 1, b_row = lane & 7;
    const int b_col8 = ((lane >> 3) & 1) * 8;

    const __half* Qg  = g_qh + (size_t)bh * Tc * HDc;
    const __half* Kg  = g_kh + (size_t)bh * Tc * HDc;
    const __half* Vtg = g_vt + (size_t)bh * HDc * Tc;
    __half*       Og  = g_ch + (size_t)bh * Tc * HDc;

    __half* Ps = fsm + HPS;
    const uint32_t psb = sb + HPS * 2u;

    // Q fragments (pre-scaled by CSC at projection), held all loop
    uint32_t qf[8][4];
    {
        const int r0 = qb + wq + g, r1 = r0 + 8;
#pragma unroll
        for (int ds = 0; ds < 8; ds++) {
            qf[ds][0] = *(const uint32_t*)&Qg[(size_t)r0 * HDc + ds * 16 + 2 * t];
            qf[ds][1] = *(const uint32_t*)&Qg[(size_t)r1 * HDc + ds * 16 + 2 * t];
            qf[ds][2] = *(const uint32_t*)&Qg[(size_t)r0 * HDc + ds * 16 + 8 + 2 * t];
            qf[ds][3] = *(const uint32_t*)&Qg[(size_t)r1 * HDc + ds * 16 + 8 + 2 * t];
        }
    }

    float o[16][4];
#pragma unroll
    for (int nt = 0; nt < 16; nt++)
#pragma unroll
        for (int j = 0; j < 4; j++) o[nt][j] = 0.f;

    float m0 = -1e30f, m1 = -1e30f, l0 = 0.f, l1 = 0.f;
    const int ktmax = qt;

    auto issue_kv = [&](int buf, int kt) {
        const int kb = kt * 64;
        const uint32_t kd = sb + (buf ? HK1 : HK0) * 2u;
        const uint32_t vd = sb + (buf ? HV1 : HV0) * 2u;
#pragma unroll
        for (int it = 0; it < 8; it++) {
            const int idx = tid + it * 128;          // 0..1023
            const int c = idx >> 4, s = idx & 15;
            cp16(kd + (uint32_t)(c * 136 + s * 8) * 2u,
                 Kg + (size_t)(kb + c) * HDc + s * 8);
        }
#pragma unroll
        for (int it = 0; it < 8; it++) {
            const int idx = tid + it * 128;          // 0..1023
            const int d = idx >> 3, s = idx & 7;
            cp16(vd + (uint32_t)(d * 72 + s * 8) * 2u,
                 Vtg + (size_t)d * Tc + kb + s * 8);
        }
        CP_COMMIT();
    };

    issue_kv(0, 0);

    for (int kt = 0; kt <= ktmax; kt++) {
        const int cur = kt & 1;
        CP_WAIT0();
        __syncthreads();
        if (kt < ktmax) issue_kv(1 - cur, kt + 1);

        const uint32_t ks_b = sb + (cur ? HK1 : HK0) * 2u;
        const uint32_t vs_b = sb + (cur ? HV1 : HV0) * 2u;
        const int kb = kt * 64;

        const bool needm = (kt == qt);
        const int jmax = needm ? wid : 3;   // guard value; loops stay unrolled

        // S = Q K^T : warp 16q x 64c (diagonal chunks j>wid skipped by guard)
        float s[8][4];
#pragma unroll
        for (int nt = 0; nt < 8; nt++)
#pragma unroll
            for (int j = 0; j < 4; j++) s[nt][j] = 0.f;

#pragma unroll
        for (int ds = 0; ds < 8; ds++) {
#pragma unroll
            for (int j = 0; j < 4; j++) {
                if (j <= jmax) {
                    uint32_t br[4];
                    ldm4(ks_b + (uint32_t)(((2 * j + b_rgrp) * 8 + b_row) * 136
                                           + ds * 16 + b_col8) * 2u, br);
                    mma16(s[2 * j],     qf[ds], br[0], br[1]);
                    mma16(s[2 * j + 1], qf[ds], br[2], br[3]);
                }
            }
        }

        // causal mask (diagonal tile only); scale already folded into Q
        const int qr0 = qb + wq + g, qr1 = qr0 + 8;
        if (needm) {
#pragma unroll
            for (int nt = 0; nt < 8; nt++) {
                const int c0 = kb + nt * 8 + 2 * t;
                if (c0     > qr0) s[nt][0] = -1e30f;
                if (c0 + 1 > qr0) s[nt][1] = -1e30f;
                if (c0     > qr1) s[nt][2] = -1e30f;
                if (c0 + 1 > qr1) s[nt][3] = -1e30f;
            }
        }

        // online softmax (log2 domain)
        float mx0 = -1e30f, mx1 = -1e30f;
#pragma unroll
        for (int nt = 0; nt < 8; nt++) {
            mx0 = fmaxf(mx0, fmaxf(s[nt][0], s[nt][1]));
            mx1 = fmaxf(mx1, fmaxf(s[nt][2], s[nt][3]));
        }
        mx0 = fmaxf(mx0, __shfl_xor_sync(0xffffffffu, mx0, 1));
        mx0 = fmaxf(mx0, __shfl_xor_sync(0xffffffffu, mx0, 2));
        mx1 = fmaxf(mx1, __shfl_xor_sync(0xffffffffu, mx1, 1));
        mx1 = fmaxf(mx1, __shfl_xor_sync(0xffffffffu, mx1, 2));

        const float mn0 = fmaxf(m0, mx0), mn1 = fmaxf(m1, mx1);
        const float a0 = ex2(m0 - mn0), a1 = ex2(m1 - mn1);

        float ls0 = 0.f, ls1 = 0.f;
#pragma unroll
        for (int nt = 0; nt < 8; nt++) {
            const float p0 = ex2(s[nt][0] - mn0);
            const float p1 = ex2(s[nt][1] - mn0);
            const float p2 = ex2(s[nt][2] - mn1);
            const float p3 = ex2(s[nt][3] - mn1);
            ls0 += p0 + p1; ls1 += p2 + p3;
            *(uint32_t*)&Ps[(wq + g) * 72 + nt * 8 + 2 * t]     = h2u(p0, p1);
            *(uint32_t*)&Ps[(wq + g + 8) * 72 + nt * 8 + 2 * t] = h2u(p2, p3);
        }
        ls0 += __shfl_xor_sync(0xffffffffu, ls0, 1);
        ls0 += __shfl_xor_sync(0xffffffffu, ls0, 2);
        ls1 += __shfl_xor_sync(0xffffffffu, ls1, 1);
        ls1 += __shfl_xor_sync(0xffffffffu, ls1, 2);
        l0 = l0 * a0 + ls0;
        l1 = l1 * a1 + ls1;
        m0 = mn0; m1 = mn1;

#pragma unroll
        for (int nt = 0; nt < 16; nt++) {
            o[nt][0] *= a0; o[nt][1] *= a0;
            o[nt][2] *= a1; o[nt][3] *= a1;
        }
        __syncwarp();    // Ps stores (cross-lane) visible to ldmatrix

        // O += P V (P chunks ks>jmax are all-zero on diagonal; guarded skip)
#pragma unroll
        for (int ks = 0; ks < 4; ks++) {
            if (ks <= jmax) {
                uint32_t pa[4];
                ldm4(psb + (uint32_t)((wq + a_row) * 72 + ks * 16 + a_col8) * 2u,
                     pa);
#pragma unroll
                for (int j = 0; j < 8; j++) {
                    uint32_t vb[4];
                    ldm4(vs_b + (uint32_t)(((2 * j + b_rgrp) * 8 + b_row) * 72
                                           + ks * 16 + b_col8) * 2u, vb);
                    mma16(o[2 * j],     pa, vb[0], vb[1]);
                    mma16(o[2 * j + 1], pa, vb[2], vb[3]);
                }
            }
        }
    }

    // epilogue
    const float il0 = 1.f / l0, il1 = 1.f / l1;
    const int r0 = qb + wq + g, r1 = r0 + 8;
#pragma unroll
    for (int nt = 0; nt < 16; nt++) {
        const int c = nt * 8 + 2 * t;
        *(uint32_t*)&Og[(size_t)r0 * HDc + c] = h2u(o[nt][0] * il0, o[nt][1] * il0);
        *(uint32_t*)&Og[(size_t)r1 * HDc + c] = h2u(o[nt][2] * il1, o[nt][3] * il1);
    }
}

// ---------------------------------------------------------------------------
extern "C" void kernel_launch(void* const* d_in, const int* in_sizes, int n_in,
                              void* d_out, int out_size)
{
    const float* x  = (const float*)d_in[0];
    const float* y  = (const float*)d_in[1];
    const float* Wq = (const float*)d_in[2];
    const float* bq = (const float*)d_in[3];
    const float* Wk = (const float*)d_in[4];
    const float* bk = (const float*)d_in[5];
    const float* Wv = (const float*)d_in[6];
    const float* bv = (const float*)d_in[7];
    const float* Wo = (const float*)d_in[8];
    const float* bo = (const float*)d_in[9];
    float* out = (float*)d_out;

    cudaFuncSetAttribute(flash_attn,
                         cudaFuncAttributeMaxDynamicSharedMemorySize, FLASH_SMEM);
    cudaFuncSetAttribute(gemm_qkv,
                         cudaFuncAttributeMaxDynamicSharedMemorySize, GEMM_SMEM);
    cudaFuncSetAttribute(gemm_out,
                         cudaFuncAttributeMaxDynamicSharedMemorySize, GOUT_SMEM);

    __half* gx; cudaGetSymbolAddress((void**)&gx, g_xh);
    __half* gy; cudaGetSymbolAddress((void**)&gy, g_yh);
    __half* gw; cudaGetSymbolAddress((void**)&gw, g_wh);
    __half* gq; cudaGetSymbolAddress((void**)&gq, g_qh);
    __half* gk; cudaGetSymbolAddress((void**)&gk, g_kh);
    __half* gvt; cudaGetSymbolAddress((void**)&gvt, g_vt);
    __half* gc; cudaGetSymbolAddress((void**)&gc, g_ch);

    // 1. convert inputs + weights to fp16
    const int nXY4 = (Mc * Dc) / 4;
    const int nW4  = (Dc * Dc) / 4;
    conv_h2<<<dim3((nXY4 + 255)/256, 2), 256>>>(
        (const float4*)x, (uint2*)gx, (const float4*)y, (uint2*)gy, nXY4);
    conv_h4<<<dim3((nW4 + 255)/256, 4), 256>>>(
        (const float4*)Wq, (const float4*)Wk, (const float4*)Wv,
        (const float4*)Wo, (uint2*)gw, nW4);

    // 2. fused Q/K/V projections (single launch, 1536 CTAs)
    dim3 gblk(256);
    dim3 qkvgrid(Dc/128, Mc/128, 3);   // (8, 64, 3)
    gemm_qkv<<<qkvgrid, gblk, GEMM_SMEM>>>(gx, gy, gw, bq, bk, bv,
                                           gq, gk, gvt);

    // 3. attention
    dim3 fgrid(Tc/64, Bc*Hc);     // (32, 32) = 1024 CTAs
    flash_attn<<<fgrid, dim3(128), FLASH_SMEM>>>();

    // 4. output projection (BM=64, 1024 CTAs)
    dim3 ogrid(Dc/128, Mc/64);    // (8, 128)
    gemm_out<<<ogrid, dim3(128), GOUT_SMEM>>>(gc, gw + 3*Dc*Dc, bo, out);
}

// round 15
// speedup vs baseline: 1.6513x; 1.0467x over previous
#include <cuda_runtime.h>
#include <cuda_fp16.h>
#include <math.h>
#include <stdint.h>

#define Bc  4
#define Tc  2048
#define Dc  1024
#define Hc  8
#define HDc 128
#define Mc  (Bc*Tc)

// Scratch (fp16)
__device__ __half g_qh[Bc*Tc*Dc];           // [B,H,T,HD], pre-scaled by c*log2e
__device__ __half g_kh[Bc*Tc*Dc];           // [B,H,T,HD]
__device__ __half g_vt[Bc*Tc*Dc];           // [B,H,HD,T]  (V transposed)
__device__ __half g_ch[Bc*Tc*Dc];           // ctx [B,H,T,HD]
__device__ __half g_xh[Bc*Tc*Dc];
__device__ __half g_yh[Bc*Tc*Dc];
__device__ __half g_wh[4][Dc*Dc];

// ---------------------------------------------------------------------------
// helpers
// ---------------------------------------------------------------------------
__device__ __forceinline__ uint32_t smem_u32(const void* p) {
    uint32_t a;
    asm("{ .reg .u64 t; cvta.to.shared.u64 t, %1; cvt.u32.u64 %0, t; }"
        : "=r"(a) : "l"(p));
    return a;
}
__device__ __forceinline__ float ex2(float x) {
    float y;
    asm("ex2.approx.f32 %0, %1;" : "=f"(y) : "f"(x));
    return y;
}
__device__ __forceinline__ uint32_t h2u(float a, float b) {
    __half2 h = __floats2half2_rn(a, b);
    return *(uint32_t*)&h;
}
__device__ __forceinline__ void cp16(uint32_t dst, const void* src) {
    asm volatile("cp.async.cg.shared.global [%0], [%1], 16;" :: "r"(dst), "l"(src));
}
#define CP_COMMIT() asm volatile("cp.async.commit_group;" ::: "memory")
#define CP_WAIT1()  asm volatile("cp.async.wait_group 1;" ::: "memory")
#define CP_WAIT0()  asm volatile("cp.async.wait_group 0;" ::: "memory")

// ldmatrix x4 (b16, non-trans)
__device__ __forceinline__ void ldm4(uint32_t addr, uint32_t* r) {
    asm volatile("ldmatrix.sync.aligned.m8n8.x4.shared.b16 {%0,%1,%2,%3}, [%4];"
                 : "=r"(r[0]), "=r"(r[1]), "=r"(r[2]), "=r"(r[3]) : "r"(addr));
}

// m16n8k16 fp16 MMA, f32 accumulate in place.
__device__ __forceinline__ void mma16(float* d, const uint32_t* a,
                                      uint32_t b0, uint32_t b1) {
    asm volatile(
        "mma.sync.aligned.m16n8k16.row.col.f32.f16.f16.f32 "
        "{%0,%1,%2,%3}, {%4,%5,%6,%7}, {%8,%9}, {%0,%1,%2,%3};"
        : "+f"(d[0]), "+f"(d[1]), "+f"(d[2]), "+f"(d[3])
        : "r"(a[0]), "r"(a[1]), "r"(a[2]), "r"(a[3]), "r"(b0), "r"(b1));
}

#define CSC 0.12751743342f   // (1/sqrt(128)) * log2(e)

// ---------------------------------------------------------------------------
// fp32 -> fp16 convert, single launch: y 0..1 = x/y inputs (n4 = nXY4),
// y 2..5 = Wq/Wk/Wv/Wo (n4w = nW4)
// ---------------------------------------------------------------------------
__global__ void conv_all(const float4* __restrict__ x, const float4* __restrict__ y,
                         const float4* __restrict__ w0, const float4* __restrict__ w1,
                         const float4* __restrict__ w2, const float4* __restrict__ w3,
                         uint2* __restrict__ ox, uint2* __restrict__ oy,
                         uint2* __restrict__ ow, int n4xy, int n4w) {
    const int i = blockIdx.x * blockDim.x + threadIdx.x;
    const int z = blockIdx.y;
    const float4* s;
    uint2* d;
    int n4;
    if (z < 2) {
        s = z ? y : x;
        d = z ? oy : ox;
        n4 = n4xy;
    } else {
        s = (z == 2) ? w0 : (z == 3) ? w1 : (z == 4) ? w2 : w3;
        d = ow + (size_t)(z - 2) * (Dc * Dc / 4);
        n4 = n4w;
    }
    if (i < n4) {
        float4 v = s[i];
        uint2 o;
        o.x = h2u(v.x, v.y);
        o.y = h2u(v.z, v.w);
        d[i] = o;
    }
}

// ---------------------------------------------------------------------------
// Fused Q/K/V projection GEMM (blockIdx.z selects problem).
// z=0: Q = (x Wq^T + bq)*CSC -> g_qh   (scale folded for flash)
// z=1: K = y Wk^T + bk       -> g_kh
// z=2: V = y Wv^T + bv       -> g_vt (V^T layout, smem-staged transpose)
// ---------------------------------------------------------------------------
#define GEMM_SMEM (3*20480)

__global__ __launch_bounds__(256, 2)
void gemm_qkv(const __half* __restrict__ Ax, const __half* __restrict__ Ay,
              const __half* __restrict__ gw,
              const float* __restrict__ bq, const float* __restrict__ bk,
              const float* __restrict__ bv,
              __half* __restrict__ gq, __half* __restrict__ gk,
              __half* __restrict__ gvt)
{
    extern __shared__ __align__(16) char smemc[];
    const uint32_t sb = smem_u32(smemc);

    const int z = blockIdx.z;
    const __half* A    = (z == 0) ? Ax : Ay;
    const __half* Wg   = gw + (size_t)z * Dc * Dc;
    const float*  bias = (z == 0) ? bq : (z == 1) ? bk : bv;
    __half*       outh = (z == 0) ? gq : (z == 1) ? gk : gvt;
    const float   osc  = (z == 0) ? CSC : 1.0f;

    const int tid = threadIdx.x;
    const int wid = tid >> 5, lane = tid & 31;
    const int g = lane >> 2, t = lane & 3;
    const int wm = (wid & 3) * 32, wn = (wid >> 2) * 64;
    const int bn = blockIdx.x * 128, bm = blockIdx.y * 128;

    const int a_row = lane & 15, a_col8 = ((lane >> 4) & 1) * 8;
    const int b_rgrp = (lane >> 4) & 1, b_row = lane & 7;
    const int b_col8 = ((lane >> 3) & 1) * 8;

    auto issue = [&](int stg, int k0) {
        const uint32_t da = sb + (uint32_t)(stg * 20480);
        const uint32_t db = da + 10240u;
#pragma unroll
        for (int it = 0; it < 2; it++) {
            const int idx = tid + it * 256;          // 0..511
            const int row = idx >> 2, s = idx & 3;
            cp16(da + (uint32_t)(row * 40 + s * 8) * 2u,
                 A + (size_t)(bm + row) * Dc + k0 + s * 8);
        }
#pragma unroll
        for (int it = 0; it < 2; it++) {
            const int idx = tid + it * 256;
            const int row = idx >> 2, s = idx & 3;
            cp16(db + (uint32_t)(row * 40 + s * 8) * 2u,
                 Wg + (size_t)(bn + row) * Dc + k0 + s * 8);
        }
        CP_COMMIT();
    };

    float c[2][8][4];
#pragma unroll
    for (int mt = 0; mt < 2; mt++)
#pragma unroll
        for (int nt = 0; nt < 8; nt++)
#pragma unroll
            for (int j = 0; j < 4; j++) c[mt][nt][j] = 0.f;

    issue(0, 0); issue(1, 32);

    for (int i = 0; i < 32; i++) {
        if (i == 31) { CP_WAIT0(); } else { CP_WAIT1(); }
        __syncthreads();
        if (i + 2 < 32) issue((i + 2) % 3, (i + 2) * 32);

        const uint32_t as = sb + (uint32_t)((i % 3) * 20480);
        const uint32_t bs = as + 10240u;

#pragma unroll
        for (int ks = 0; ks < 2; ks++) {
            const int kk = ks * 16;
            uint32_t a[2][4];
#pragma unroll
            for (int mt = 0; mt < 2; mt++)
                ldm4(as + (uint32_t)((wm + mt * 16 + a_row) * 40 + kk + a_col8) * 2u,
                     a[mt]);
#pragma unroll
            for (int j = 0; j < 4; j++) {
                uint32_t br[4];
                ldm4(bs + (uint32_t)((wn + (2 * j + b_rgrp) * 8 + b_row) * 40
                                     + kk + b_col8) * 2u, br);
#pragma unroll
                for (int mt = 0; mt < 2; mt++) {
                    mma16(c[mt][2 * j],     a[mt], br[0], br[1]);
                    mma16(c[mt][2 * j + 1], a[mt], br[2], br[3]);
                }
            }
        }
    }
    __syncthreads();   // protect smem reuse by z==2 epilogue staging

    const int b0i_base = bm >> 11, t0 = bm & 2047;
    const int h = bn >> 7;

    if (z == 2) {
        __half* Ts = (__half*)smemc;          // [128 n][136] halves
#pragma unroll
        for (int mt = 0; mt < 2; mt++) {
            const int r0l = wm + mt * 16 + g, r1l = r0l + 8;
#pragma unroll
            for (int nt = 0; nt < 8; nt++) {
                const int cl = wn + nt * 8 + 2 * t;
                const float bx = __ldg(bias + bn + cl);
                const float by = __ldg(bias + bn + cl + 1);
                Ts[(cl    ) * 136 + r0l] = __float2half_rn(c[mt][nt][0] + bx);
                Ts[(cl + 1) * 136 + r0l] = __float2half_rn(c[mt][nt][1] + by);
                Ts[(cl    ) * 136 + r1l] = __float2half_rn(c[mt][nt][2] + bx);
                Ts[(cl + 1) * 136 + r1l] = __float2half_rn(c[mt][nt][3] + by);
            }
        }
        __syncthreads();
#pragma unroll
        for (int it = 0; it < 8; it++) {
            const int idx = tid + it * 256;          // 0..2047
            const int row = idx >> 4, s = idx & 15;
            const uint4 v = *(const uint4*)&Ts[row * 136 + s * 8];
            *(uint4*)&outh[(((size_t)(b0i_base * Hc + h) * HDc + row)
                            * Tc) + t0 + s * 8] = v;
        }
        return;
    }

#pragma unroll
    for (int mt = 0; mt < 2; mt++) {
        const int r0 = bm + wm + mt * 16 + g;
        const int r1 = r0 + 8;
#pragma unroll
        for (int nt = 0; nt < 8; nt++) {
            const int cl = wn + nt * 8 + 2 * t;
            const int col = bn + cl;
            const float bx = __ldg(bias + col), by = __ldg(bias + col + 1);
            const float v00 = (c[mt][nt][0] + bx) * osc;
            const float v01 = (c[mt][nt][1] + by) * osc;
            const float v10 = (c[mt][nt][2] + bx) * osc;
            const float v11 = (c[mt][nt][3] + by) * osc;
            const int b0i = r0 >> 11, t0i = r0 & 2047;
            const int b1i = r1 >> 11, t1i = r1 & 2047;
            *(uint32_t*)&outh[(((size_t)(b0i * Hc + h) * Tc + t0i) * HDc) + cl]
                = h2u(v00, v01);
            *(uint32_t*)&outh[(((size_t)(b1i * Hc + h) * Tc + t1i) * HDc) + cl]
                = h2u(v10, v11);
        }
    }
}

// ---------------------------------------------------------------------------
// Output projection GEMM: out = ctx Wo^T + bo (fp32)
// CTA: 128 threads (4 warps), tile 64(M) x 128(N); warp 32x64; 4 CTAs/SM.
// ---------------------------------------------------------------------------
#define GOUT_SMEM (3*15360)

__global__ __launch_bounds__(128, 4)
void gemm_out(const __half* __restrict__ A, const __half* __restrict__ Wg,
              const float* __restrict__ bias, float* __restrict__ outf)
{
    extern __shared__ __align__(16) char smemc[];
    const uint32_t sb = smem_u32(smemc);

    const int tid = threadIdx.x;
    const int wid = tid >> 5, lane = tid & 31;
    const int g = lane >> 2, t = lane & 3;
    const int wm = (wid & 1) * 32, wn = (wid >> 1) * 64;
    const int bn = blockIdx.x * 128, bm = blockIdx.y * 64;

    const int a_row = lane & 15, a_col8 = ((lane >> 4) & 1) * 8;
    const int b_rgrp = (lane >> 4) & 1, b_row = lane & 7;
    const int b_col8 = ((lane >> 3) & 1) * 8;

    auto issue = [&](int stg, int k0) {
        const uint32_t da = sb + (uint32_t)(stg * 15360);
        const uint32_t db = da + 5120u;
#pragma unroll
        for (int it = 0; it < 2; it++) {
            const int idx = tid + it * 128;          // 0..255
            const int row = idx >> 2, s = idx & 3;
            const int m = bm + row, b = m >> 11, tt = m & 2047;
            const int kg = k0 + s * 8;
            const int h = kg >> 7, d = kg & 127;
            cp16(da + (uint32_t)(row * 40 + s * 8) * 2u,
                 A + (((size_t)(b * Hc + h) * Tc + tt) * HDc + d));
        }
#pragma unroll
        for (int it = 0; it < 4; it++) {
            const int idx = tid + it * 128;          // 0..511
            const int row = idx >> 2, s = idx & 3;
            cp16(db + (uint32_t)(row * 40 + s * 8) * 2u,
                 Wg + (size_t)(bn + row) * Dc + k0 + s * 8);
        }
        CP_COMMIT();
    };

    float c[2][8][4];
#pragma unroll
    for (int mt = 0; mt < 2; mt++)
#pragma unroll
        for (int nt = 0; nt < 8; nt++)
#pragma unroll
            for (int j = 0; j < 4; j++) c[mt][nt][j] = 0.f;

    issue(0, 0); issue(1, 32);

    for (int i = 0; i < 32; i++) {
        if (i == 31) { CP_WAIT0(); } else { CP_WAIT1(); }
        __syncthreads();
        if (i + 2 < 32) issue((i + 2) % 3, (i + 2) * 32);

        const uint32_t as = sb + (uint32_t)((i % 3) * 15360);
        const uint32_t bs = as + 5120u;

#pragma unroll
        for (int ks = 0; ks < 2; ks++) {
            const int kk = ks * 16;
            uint32_t a[2][4];
#pragma unroll
            for (int mt = 0; mt < 2; mt++)
                ldm4(as + (uint32_t)((wm + mt * 16 + a_row) * 40 + kk + a_col8) * 2u,
                     a[mt]);
#pragma unroll
            for (int j = 0; j < 4; j++) {
                uint32_t br[4];
                ldm4(bs + (uint32_t)((wn + (2 * j + b_rgrp) * 8 + b_row) * 40
                                     + kk + b_col8) * 2u, br);
#pragma unroll
                for (int mt = 0; mt < 2; mt++) {
                    mma16(c[mt][2 * j],     a[mt], br[0], br[1]);
                    mma16(c[mt][2 * j + 1], a[mt], br[2], br[3]);
                }
            }
        }
    }

#pragma unroll
    for (int mt = 0; mt < 2; mt++) {
        const int r0 = bm + wm + mt * 16 + g;
        const int r1 = r0 + 8;
#pragma unroll
        for (int nt = 0; nt < 8; nt++) {
            const int cl = wn + nt * 8 + 2 * t;
            const int col = bn + cl;
            const float bx = __ldg(bias + col), by = __ldg(bias + col + 1);
            *(float2*)&outf[(size_t)r0 * Dc + col]
                = make_float2(c[mt][nt][0] + bx, c[mt][nt][1] + by);
            *(float2*)&outf[(size_t)r1 * Dc + col]
                = make_float2(c[mt][nt][2] + bx, c[mt][nt][3] + by);
        }
    }
}

// ---------------------------------------------------------------------------
// Flash attention fp16 (ROUND-12 STRUCTURE, Q pre-scaled, NO culling):
// 128 threads / 4 warps; Q tile 64 (warp 16 q-rows), K tile 64; ldmatrix
// K/V/P fragments; P via smem; double-buffered K/V; reversed qt; 2 CTAs/SM.
// ---------------------------------------------------------------------------
#define FLASH_SMEM 80896
#define HK0  0
#define HK1  8704
#define HV0  17408
#define HV1  26624
#define HPS  35840

__global__ __launch_bounds__(128, 2)
void flash_attn()
{
    extern __shared__ __align__(16) __half fsm[];
    const uint32_t sb = smem_u32(fsm);

    const int bh  = blockIdx.y;
    const int qt  = gridDim.x - 1 - blockIdx.x;    // longest blocks first
    const int qb  = qt * 64;
    const int tid = threadIdx.x;
    const int wid = tid >> 5, lane = tid & 31;
    const int g = lane >> 2, t = lane & 3;
    const int wq = wid * 16;

    const int a_row = lane & 15, a_col8 = ((lane >> 4) & 1) * 8;
    const int b_rgrp = (lane >> 4) & 1, b_row = lane & 7;
    const int b_col8 = ((lane >> 3) & 1) * 8;

    const __half* Qg  = g_qh + (size_t)bh * Tc * HDc;
    const __half* Kg  = g_kh + (size_t)bh * Tc * HDc;
    const __half* Vtg = g_vt + (size_t)bh * HDc * Tc;
    __half*       Og  = g_ch + (size_t)bh * Tc * HDc;

    __half* Ps = fsm + HPS;
    const uint32_t psb = sb + HPS * 2u;

    // Q fragments (pre-scaled by CSC at projection), held all loop
    uint32_t qf[8][4];
    {
        const int r0 = qb + wq + g, r1 = r0 + 8;
#pragma unroll
        for (int ds = 0; ds < 8; ds++) {
            qf[ds][0] = *(const uint32_t*)&Qg[(size_t)r0 * HDc + ds * 16 + 2 * t];
            qf[ds][1] = *(const uint32_t*)&Qg[(size_t)r1 * HDc + ds * 16 + 2 * t];
            qf[ds][2] = *(const uint32_t*)&Qg[(size_t)r0 * HDc + ds * 16 + 8 + 2 * t];
            qf[ds][3] = *(const uint32_t*)&Qg[(size_t)r1 * HDc + ds * 16 + 8 + 2 * t];
        }
    }

    float o[16][4];
#pragma unroll
    for (int nt = 0; nt < 16; nt++)
#pragma unroll
        for (int j = 0; j < 4; j++) o[nt][j] = 0.f;

    float m0 = -1e30f, m1 = -1e30f, l0 = 0.f, l1 = 0.f;
    const int ktmax = qt;

    auto issue_kv = [&](int buf, int kt) {
        const int kb = kt * 64;
        const uint32_t kd = sb + (buf ? HK1 : HK0) * 2u;
        const uint32_t vd = sb + (buf ? HV1 : HV0) * 2u;
#pragma unroll
        for (int it = 0; it < 8; it++) {
            const int idx = tid + it * 128;          // 0..1023
            const int c = idx >> 4, s = idx & 15;
            cp16(kd + (uint32_t)(c * 136 + s * 8) * 2u,
                 Kg + (size_t)(kb + c) * HDc + s * 8);
        }
#pragma unroll
        for (int it = 0; it < 8; it++) {
            const int idx = tid + it * 128;          // 0..1023
            const int d = idx >> 3, s = idx & 7;
            cp16(vd + (uint32_t)(d * 72 + s * 8) * 2u,
                 Vtg + (size_t)d * Tc + kb + s * 8);
        }
        CP_COMMIT();
    };

    issue_kv(0, 0);

    for (int kt = 0; kt <= ktmax; kt++) {
        const int cur = kt & 1;
        CP_WAIT0();
        __syncthreads();
        if (kt < ktmax) issue_kv(1 - cur, kt + 1);

        const uint32_t ks_b = sb + (cur ? HK1 : HK0) * 2u;
        const uint32_t vs_b = sb + (cur ? HV1 : HV0) * 2u;
        const int kb = kt * 64;

        // S = Q K^T : warp 16q x 64c
        float s[8][4];
#pragma unroll
        for (int nt = 0; nt < 8; nt++)
#pragma unroll
            for (int j = 0; j < 4; j++) s[nt][j] = 0.f;

#pragma unroll
        for (int ds = 0; ds < 8; ds++) {
#pragma unroll
            for (int j = 0; j < 4; j++) {
                uint32_t br[4];
                ldm4(ks_b + (uint32_t)(((2 * j + b_rgrp) * 8 + b_row) * 136
                                       + ds * 16 + b_col8) * 2u, br);
                mma16(s[2 * j],     qf[ds], br[0], br[1]);
                mma16(s[2 * j + 1], qf[ds], br[2], br[3]);
            }
        }

        // causal mask (diagonal tile only); scale already folded into Q
        const int qr0 = qb + wq + g, qr1 = qr0 + 8;
        if (kt == qt) {
#pragma unroll
            for (int nt = 0; nt < 8; nt++) {
                const int c0 = kb + nt * 8 + 2 * t;
                if (c0     > qr0) s[nt][0] = -1e30f;
                if (c0 + 1 > qr0) s[nt][1] = -1e30f;
                if (c0     > qr1) s[nt][2] = -1e30f;
                if (c0 + 1 > qr1) s[nt][3] = -1e30f;
            }
        }

        // online softmax (log2 domain)
        float mx0 = -1e30f, mx1 = -1e30f;
#pragma unroll
        for (int nt = 0; nt < 8; nt++) {
            mx0 = fmaxf(mx0, fmaxf(s[nt][0], s[nt][1]));
            mx1 = fmaxf(mx1, fmaxf(s[nt][2], s[nt][3]));
        }
        mx0 = fmaxf(mx0, __shfl_xor_sync(0xffffffffu, mx0, 1));
        mx0 = fmaxf(mx0, __shfl_xor_sync(0xffffffffu, mx0, 2));
        mx1 = fmaxf(mx1, __shfl_xor_sync(0xffffffffu, mx1, 1));
        mx1 = fmaxf(mx1, __shfl_xor_sync(0xffffffffu, mx1, 2));

        const float mn0 = fmaxf(m0, mx0), mn1 = fmaxf(m1, mx1);
        const float a0 = ex2(m0 - mn0), a1 = ex2(m1 - mn1);

        float ls0 = 0.f, ls1 = 0.f;
#pragma unroll
        for (int nt = 0; nt < 8; nt++) {
            const float p0 = ex2(s[nt][0] - mn0);
            const float p1 = ex2(s[nt][1] - mn0);
            const float p2 = ex2(s[nt][2] - mn1);
            const float p3 = ex2(s[nt][3] - mn1);
            ls0 += p0 + p1; ls1 += p2 + p3;
            *(uint32_t*)&Ps[(wq + g) * 72 + nt * 8 + 2 * t]     = h2u(p0, p1);
            *(uint32_t*)&Ps[(wq + g + 8) * 72 + nt * 8 + 2 * t] = h2u(p2, p3);
        }
        ls0 += __shfl_xor_sync(0xffffffffu, ls0, 1);
        ls0 += __shfl_xor_sync(0xffffffffu, ls0, 2);
        ls1 += __shfl_xor_sync(0xffffffffu, ls1, 1);
        ls1 += __shfl_xor_sync(0xffffffffu, ls1, 2);
        l0 = l0 * a0 + ls0;
        l1 = l1 * a1 + ls1;
        m0 = mn0; m1 = mn1;

#pragma unroll
        for (int nt = 0; nt < 16; nt++) {
            o[nt][0] *= a0; o[nt][1] *= a0;
            o[nt][2] *= a1; o[nt][3] *= a1;
        }
        __syncwarp();    // Ps stores (cross-lane) visible to ldmatrix

        // O += P V : warp 16q x 128d
#pragma unroll
        for (int ks = 0; ks < 4; ks++) {
            uint32_t pa[4];
            ldm4(psb + (uint32_t)((wq + a_row) * 72 + ks * 16 + a_col8) * 2u,
                 pa);
#pragma unroll
            for (int j = 0; j < 8; j++) {
                uint32_t vb[4];
                ldm4(vs_b + (uint32_t)(((2 * j + b_rgrp) * 8 + b_row) * 72
                                       + ks * 16 + b_col8) * 2u, vb);
                mma16(o[2 * j],     pa, vb[0], vb[1]);
                mma16(o[2 * j + 1], pa, vb[2], vb[3]);
            }
        }
    }

    // epilogue
    const float il0 = 1.f / l0, il1 = 1.f / l1;
    const int r0 = qb + wq + g, r1 = r0 + 8;
#pragma unroll
    for (int nt = 0; nt < 16; nt++) {
        const int c = nt * 8 + 2 * t;
        *(uint32_t*)&Og[(size_t)r0 * HDc + c] = h2u(o[nt][0] * il0, o[nt][1] * il0);
        *(uint32_t*)&Og[(size_t)r1 * HDc + c] = h2u(o[nt][2] * il1, o[nt][3] * il1);
    }
}

// ---------------------------------------------------------------------------
extern "C" void kernel_launch(void* const* d_in, const int* in_sizes, int n_in,
                              void* d_out, int out_size)
{
    const float* x  = (const float*)d_in[0];
    const float* y  = (const float*)d_in[1];
    const float* Wq = (const float*)d_in[2];
    const float* bq = (const float*)d_in[3];
    const float* Wk = (const float*)d_in[4];
    const float* bk = (const float*)d_in[5];
    const float* Wv = (const float*)d_in[6];
    const float* bv = (const float*)d_in[7];
    const float* Wo = (const float*)d_in[8];
    const float* bo = (const float*)d_in[9];
    float* out = (float*)d_out;

    cudaFuncSetAttribute(flash_attn,
                         cudaFuncAttributeMaxDynamicSharedMemorySize, FLASH_SMEM);
    cudaFuncSetAttribute(gemm_qkv,
                         cudaFuncAttributeMaxDynamicSharedMemorySize, GEMM_SMEM);
    cudaFuncSetAttribute(gemm_out,
                         cudaFuncAttributeMaxDynamicSharedMemorySize, GOUT_SMEM);

    __half* gx; cudaGetSymbolAddress((void**)&gx, g_xh);
    __half* gy; cudaGetSymbolAddress((void**)&gy, g_yh);
    __half* gw; cudaGetSymbolAddress((void**)&gw, g_wh);
    __half* gq; cudaGetSymbolAddress((void**)&gq, g_qh);
    __half* gk; cudaGetSymbolAddress((void**)&gk, g_kh);
    __half* gvt; cudaGetSymbolAddress((void**)&gvt, g_vt);
    __half* gc; cudaGetSymbolAddress((void**)&gc, g_ch);

    // 1. convert inputs + weights to fp16 (single launch)
    const int nXY4 = (Mc * Dc) / 4;
    const int nW4  = (Dc * Dc) / 4;
    conv_all<<<dim3((nXY4 + 255)/256, 6), 256>>>(
        (const float4*)x, (const float4*)y,
        (const float4*)Wq, (const float4*)Wk, (const float4*)Wv,
        (const float4*)Wo,
        (uint2*)gx, (uint2*)gy, (uint2*)gw, nXY4, nW4);

    // 2. fused Q/K/V projections (single launch, 1536 CTAs)
    dim3 gblk(256);
    dim3 qkvgrid(Dc/128, Mc/128, 3);   // (8, 64, 3)
    gemm_qkv<<<qkvgrid, gblk, GEMM_SMEM>>>(gx, gy, gw, bq, bk, bv,
                                           gq, gk, gvt);

    // 3. attention
    dim3 fgrid(Tc/64, Bc*Hc);     // (32, 32) = 1024 CTAs
    flash_attn<<<fgrid, dim3(128), FLASH_SMEM>>>();

    // 4. output projection (BM=64, 1024 CTAs)
    dim3 ogrid(Dc/128, Mc/64);    // (8, 128)
    gemm_out<<<ogrid, dim3(128), GOUT_SMEM>>>(gc, gw + 3*Dc*Dc, bo, out);
}

// round 16
// speedup vs baseline: 1.6786x; 1.0165x over previous
#include <cuda_runtime.h>
#include <cuda_fp16.h>
#include <math.h>
#include <stdint.h>

#define Bc  4
#define Tc  2048
#define Dc  1024
#define Hc  8
#define HDc 128
#define Mc  (Bc*Tc)

// Scratch (fp16)
__device__ __half g_qh[Bc*Tc*Dc];           // [B,H,T,HD], pre-scaled by c*log2e
__device__ __half g_kh[Bc*Tc*Dc];           // [B,H,T,HD]
__device__ __half g_vt[Bc*Tc*Dc];           // [B,H,HD,T]  (V transposed)
__device__ __half g_ch[Bc*Tc*Dc];           // ctx [B,H,T,HD]
__device__ __half g_xh[Bc*Tc*Dc];
__device__ __half g_yh[Bc*Tc*Dc];
__device__ __half g_wh[4][Dc*Dc];

// ---------------------------------------------------------------------------
// helpers
// ---------------------------------------------------------------------------
__device__ __forceinline__ uint32_t smem_u32(const void* p) {
    uint32_t a;
    asm("{ .reg .u64 t; cvta.to.shared.u64 t, %1; cvt.u32.u64 %0, t; }"
        : "=r"(a) : "l"(p));
    return a;
}
__device__ __forceinline__ float ex2(float x) {
    float y;
    asm("ex2.approx.f32 %0, %1;" : "=f"(y) : "f"(x));
    return y;
}
__device__ __forceinline__ uint32_t h2u(float a, float b) {
    __half2 h = __floats2half2_rn(a, b);
    return *(uint32_t*)&h;
}
__device__ __forceinline__ void cp16(uint32_t dst, const void* src) {
    asm volatile("cp.async.cg.shared.global [%0], [%1], 16;" :: "r"(dst), "l"(src));
}
#define CP_COMMIT() asm volatile("cp.async.commit_group;" ::: "memory")
#define CP_WAIT1()  asm volatile("cp.async.wait_group 1;" ::: "memory")
#define CP_WAIT0()  asm volatile("cp.async.wait_group 0;" ::: "memory")

// ldmatrix x4 (b16, non-trans)
__device__ __forceinline__ void ldm4(uint32_t addr, uint32_t* r) {
    asm volatile("ldmatrix.sync.aligned.m8n8.x4.shared.b16 {%0,%1,%2,%3}, [%4];"
                 : "=r"(r[0]), "=r"(r[1]), "=r"(r[2]), "=r"(r[3]) : "r"(addr));
}

// m16n8k16 fp16 MMA, f32 accumulate in place.
__device__ __forceinline__ void mma16(float* d, const uint32_t* a,
                                      uint32_t b0, uint32_t b1) {
    asm volatile(
        "mma.sync.aligned.m16n8k16.row.col.f32.f16.f16.f32 "
        "{%0,%1,%2,%3}, {%4,%5,%6,%7}, {%8,%9}, {%0,%1,%2,%3};"
        : "+f"(d[0]), "+f"(d[1]), "+f"(d[2]), "+f"(d[3])
        : "r"(a[0]), "r"(a[1]), "r"(a[2]), "r"(a[3]), "r"(b0), "r"(b1));
}

#define CSC 0.12751743342f   // (1/sqrt(128)) * log2(e)

// ---------------------------------------------------------------------------
// fp32 -> fp16 converts (2 fused launches, round-12 proven)
// ---------------------------------------------------------------------------
__global__ void conv_h2(const float4* __restrict__ a, uint2* __restrict__ oa,
                        const float4* __restrict__ b, uint2* __restrict__ ob,
                        int n4) {
    int i = blockIdx.x * blockDim.x + threadIdx.x;
    const float4* s = blockIdx.y ? b : a;
    uint2* d = blockIdx.y ? ob : oa;
    if (i < n4) {
        float4 v = s[i];
        uint2 o;
        o.x = h2u(v.x, v.y);
        o.y = h2u(v.z, v.w);
        d[i] = o;
    }
}

__global__ void conv_h4(const float4* __restrict__ w0, const float4* __restrict__ w1,
                        const float4* __restrict__ w2, const float4* __restrict__ w3,
                        uint2* __restrict__ o0, int n4) {
    int i = blockIdx.x * blockDim.x + threadIdx.x;
    const float4* s = (blockIdx.y == 0) ? w0 : (blockIdx.y == 1) ? w1
                      : (blockIdx.y == 2) ? w2 : w3;
    uint2* d = o0 + (size_t)blockIdx.y * (Dc * Dc / 4);
    if (i < n4) {
        float4 v = s[i];
        uint2 o;
        o.x = h2u(v.x, v.y);
        o.y = h2u(v.z, v.w);
        d[i] = o;
    }
}

// ---------------------------------------------------------------------------
// Fused Q/K/V projection GEMM (blockIdx.z selects problem).
// z=0: Q = (x Wq^T + bq)*CSC -> g_qh   (scale folded for flash)
// z=1: K = y Wk^T + bk       -> g_kh
// z=2: V = y Wv^T + bv       -> g_vt (V^T layout, smem-staged transpose)
// CTA tile 128x128, 8 warps (warp 32x64), K-chunk 32, 3-stage cp.async,
// ldmatrix fragments, 2 CTAs/SM, one __syncthreads per k-iter.
// ---------------------------------------------------------------------------
#define GEMM_SMEM (3*20480)

__global__ __launch_bounds__(256, 2)
void gemm_qkv(const __half* __restrict__ Ax, const __half* __restrict__ Ay,
              const __half* __restrict__ gw,
              const float* __restrict__ bq, const float* __restrict__ bk,
              const float* __restrict__ bv,
              __half* __restrict__ gq, __half* __restrict__ gk,
              __half* __restrict__ gvt)
{
    extern __shared__ __align__(16) char smemc[];
    const uint32_t sb = smem_u32(smemc);

    const int z = blockIdx.z;
    const __half* A    = (z == 0) ? Ax : Ay;
    const __half* Wg   = gw + (size_t)z * Dc * Dc;
    const float*  bias = (z == 0) ? bq : (z == 1) ? bk : bv;
    __half*       outh = (z == 0) ? gq : (z == 1) ? gk : gvt;
    const float   osc  = (z == 0) ? CSC : 1.0f;

    const int tid = threadIdx.x;
    const int wid = tid >> 5, lane = tid & 31;
    const int g = lane >> 2, t = lane & 3;
    const int wm = (wid & 3) * 32, wn = (wid >> 2) * 64;
    const int bn = blockIdx.x * 128, bm = blockIdx.y * 128;

    const int a_row = lane & 15, a_col8 = ((lane >> 4) & 1) * 8;
    const int b_rgrp = (lane >> 4) & 1, b_row = lane & 7;
    const int b_col8 = ((lane >> 3) & 1) * 8;

    auto issue = [&](int stg, int k0) {
        const uint32_t da = sb + (uint32_t)(stg * 20480);
        const uint32_t db = da + 10240u;
#pragma unroll
        for (int it = 0; it < 2; it++) {
            const int idx = tid + it * 256;          // 0..511
            const int row = idx >> 2, s = idx & 3;
            cp16(da + (uint32_t)(row * 40 + s * 8) * 2u,
                 A + (size_t)(bm + row) * Dc + k0 + s * 8);
        }
#pragma unroll
        for (int it = 0; it < 2; it++) {
            const int idx = tid + it * 256;
            const int row = idx >> 2, s = idx & 3;
            cp16(db + (uint32_t)(row * 40 + s * 8) * 2u,
                 Wg + (size_t)(bn + row) * Dc + k0 + s * 8);
        }
        CP_COMMIT();
    };

    float c[2][8][4];
#pragma unroll
    for (int mt = 0; mt < 2; mt++)
#pragma unroll
        for (int nt = 0; nt < 8; nt++)
#pragma unroll
            for (int j = 0; j < 4; j++) c[mt][nt][j] = 0.f;

    issue(0, 0); issue(1, 32);

    for (int i = 0; i < 32; i++) {
        if (i == 31) { CP_WAIT0(); } else { CP_WAIT1(); }
        __syncthreads();
        if (i + 2 < 32) issue((i + 2) % 3, (i + 2) * 32);

        const uint32_t as = sb + (uint32_t)((i % 3) * 20480);
        const uint32_t bs = as + 10240u;

#pragma unroll
        for (int ks = 0; ks < 2; ks++) {
            const int kk = ks * 16;
            uint32_t a[2][4];
#pragma unroll
            for (int mt = 0; mt < 2; mt++)
                ldm4(as + (uint32_t)((wm + mt * 16 + a_row) * 40 + kk + a_col8) * 2u,
                     a[mt]);
#pragma unroll
            for (int j = 0; j < 4; j++) {
                uint32_t br[4];
                ldm4(bs + (uint32_t)((wn + (2 * j + b_rgrp) * 8 + b_row) * 40
                                     + kk + b_col8) * 2u, br);
#pragma unroll
                for (int mt = 0; mt < 2; mt++) {
                    mma16(c[mt][2 * j],     a[mt], br[0], br[1]);
                    mma16(c[mt][2 * j + 1], a[mt], br[2], br[3]);
                }
            }
        }
    }
    __syncthreads();   // protect smem reuse by z==2 epilogue staging

    const int b0i_base = bm >> 11, t0 = bm & 2047;
    const int h = bn >> 7;

    if (z == 2) {
        __half* Ts = (__half*)smemc;          // [128 n][136] halves
#pragma unroll
        for (int mt = 0; mt < 2; mt++) {
            const int r0l = wm + mt * 16 + g, r1l = r0l + 8;
#pragma unroll
            for (int nt = 0; nt < 8; nt++) {
                const int cl = wn + nt * 8 + 2 * t;
                const float bx = __ldg(bias + bn + cl);
                const float by = __ldg(bias + bn + cl + 1);
                Ts[(cl    ) * 136 + r0l] = __float2half_rn(c[mt][nt][0] + bx);
                Ts[(cl + 1) * 136 + r0l] = __float2half_rn(c[mt][nt][1] + by);
                Ts[(cl    ) * 136 + r1l] = __float2half_rn(c[mt][nt][2] + bx);
                Ts[(cl + 1) * 136 + r1l] = __float2half_rn(c[mt][nt][3] + by);
            }
        }
        __syncthreads();
#pragma unroll
        for (int it = 0; it < 8; it++) {
            const int idx = tid + it * 256;          // 0..2047
            const int row = idx >> 4, s = idx & 15;
            const uint4 v = *(const uint4*)&Ts[row * 136 + s * 8];
            *(uint4*)&outh[(((size_t)(b0i_base * Hc + h) * HDc + row)
                            * Tc) + t0 + s * 8] = v;
        }
        return;
    }

#pragma unroll
    for (int mt = 0; mt < 2; mt++) {
        const int r0 = bm + wm + mt * 16 + g;
        const int r1 = r0 + 8;
#pragma unroll
        for (int nt = 0; nt < 8; nt++) {
            const int cl = wn + nt * 8 + 2 * t;
            const int col = bn + cl;
            const float bx = __ldg(bias + col), by = __ldg(bias + col + 1);
            const float v00 = (c[mt][nt][0] + bx) * osc;
            const float v01 = (c[mt][nt][1] + by) * osc;
            const float v10 = (c[mt][nt][2] + bx) * osc;
            const float v11 = (c[mt][nt][3] + by) * osc;
            const int b0i = r0 >> 11, t0i = r0 & 2047;
            const int b1i = r1 >> 11, t1i = r1 & 2047;
            *(uint32_t*)&outh[(((size_t)(b0i * Hc + h) * Tc + t0i) * HDc) + cl]
                = h2u(v00, v01);
            *(uint32_t*)&outh[(((size_t)(b1i * Hc + h) * Tc + t1i) * HDc) + cl]
                = h2u(v10, v11);
        }
    }
}

// ---------------------------------------------------------------------------
// Output projection GEMM (ROUND-12 PROVEN: BM=128, 256 thr, 2 CTAs/SM):
// out = ctx Wo^T + bo (fp32)
// ---------------------------------------------------------------------------
__global__ __launch_bounds__(256, 2)
void gemm_out(const __half* __restrict__ A, const __half* __restrict__ Wg,
              const float* __restrict__ bias, float* __restrict__ outf)
{
    extern __shared__ __align__(16) char smemc[];
    const uint32_t sb = smem_u32(smemc);

    const int tid = threadIdx.x;
    const int wid = tid >> 5, lane = tid & 31;
    const int g = lane >> 2, t = lane & 3;
    const int wm = (wid & 3) * 32, wn = (wid >> 2) * 64;
    const int bn = blockIdx.x * 128, bm = blockIdx.y * 128;

    const int a_row = lane & 15, a_col8 = ((lane >> 4) & 1) * 8;
    const int b_rgrp = (lane >> 4) & 1, b_row = lane & 7;
    const int b_col8 = ((lane >> 3) & 1) * 8;

    auto issue = [&](int stg, int k0) {
        const uint32_t da = sb + (uint32_t)(stg * 20480);
        const uint32_t db = da + 10240u;
#pragma unroll
        for (int it = 0; it < 2; it++) {
            const int idx = tid + it * 256;
            const int row = idx >> 2, s = idx & 3;
            const int m = bm + row, b = m >> 11, tt = m & 2047;
            const int kg = k0 + s * 8;
            const int h = kg >> 7, d = kg & 127;
            cp16(da + (uint32_t)(row * 40 + s * 8) * 2u,
                 A + (((size_t)(b * Hc + h) * Tc + tt) * HDc + d));
        }
#pragma unroll
        for (int it = 0; it < 2; it++) {
            const int idx = tid + it * 256;
            const int row = idx >> 2, s = idx & 3;
            cp16(db + (uint32_t)(row * 40 + s * 8) * 2u,
                 Wg + (size_t)(bn + row) * Dc + k0 + s * 8);
        }
        CP_COMMIT();
    };

    float c[2][8][4];
#pragma unroll
    for (int mt = 0; mt < 2; mt++)
#pragma unroll
        for (int nt = 0; nt < 8; nt++)
#pragma unroll
            for (int j = 0; j < 4; j++) c[mt][nt][j] = 0.f;

    issue(0, 0); issue(1, 32);

    for (int i = 0; i < 32; i++) {
        if (i == 31) { CP_WAIT0(); } else { CP_WAIT1(); }
        __syncthreads();
        if (i + 2 < 32) issue((i + 2) % 3, (i + 2) * 32);

        const uint32_t as = sb + (uint32_t)((i % 3) * 20480);
        const uint32_t bs = as + 10240u;

#pragma unroll
        for (int ks = 0; ks < 2; ks++) {
            const int kk = ks * 16;
            uint32_t a[2][4];
#pragma unroll
            for (int mt = 0; mt < 2; mt++)
                ldm4(as + (uint32_t)((wm + mt * 16 + a_row) * 40 + kk + a_col8) * 2u,
                     a[mt]);
#pragma unroll
            for (int j = 0; j < 4; j++) {
                uint32_t br[4];
                ldm4(bs + (uint32_t)((wn + (2 * j + b_rgrp) * 8 + b_row) * 40
                                     + kk + b_col8) * 2u, br);
#pragma unroll
                for (int mt = 0; mt < 2; mt++) {
                    mma16(c[mt][2 * j],     a[mt], br[0], br[1]);
                    mma16(c[mt][2 * j + 1], a[mt], br[2], br[3]);
                }
            }
        }
    }

#pragma unroll
    for (int mt = 0; mt < 2; mt++) {
        const int r0 = bm + wm + mt * 16 + g;
        const int r1 = r0 + 8;
#pragma unroll
        for (int nt = 0; nt < 8; nt++) {
            const int cl = wn + nt * 8 + 2 * t;
            const int col = bn + cl;
            const float bx = __ldg(bias + col), by = __ldg(bias + col + 1);
            *(float2*)&outf[(size_t)r0 * Dc + col]
                = make_float2(c[mt][nt][0] + bx, c[mt][nt][1] + by);
            *(float2*)&outf[(size_t)r1 * Dc + col]
                = make_float2(c[mt][nt][2] + bx, c[mt][nt][3] + by);
        }
    }
}

// ---------------------------------------------------------------------------
// Flash attention fp16 (ROUND-12 STRUCTURE, Q pre-scaled, no culling):
// 128 threads / 4 warps; Q tile 64 (warp 16 q-rows), K tile 64; ldmatrix
// K/V/P fragments; P via smem; double-buffered K/V; reversed qt; 2 CTAs/SM.
// ---------------------------------------------------------------------------
#define FLASH_SMEM 80896
#define HK0  0
#define HK1  8704
#define HV0  17408
#define HV1  26624
#define HPS  35840

__global__ __launch_bounds__(128, 2)
void flash_attn()
{
    extern __shared__ __align__(16) __half fsm[];
    const uint32_t sb = smem_u32(fsm);

    const int bh  = blockIdx.y;
    const int qt  = gridDim.x - 1 - blockIdx.x;    // longest blocks first
    const int qb  = qt * 64;
    const int tid = threadIdx.x;
    const int wid = tid >> 5, lane = tid & 31;
    const int g = lane >> 2, t = lane & 3;
    const int wq = wid * 16;

    const int a_row = lane & 15, a_col8 = ((lane >> 4) & 1) * 8;
    const int b_rgrp = (lane >> 4) & 1, b_row = lane & 7;
    const int b_col8 = ((lane >> 3) & 1) * 8;

    const __half* Qg  = g_qh + (size_t)bh * Tc * HDc;
    const __half* Kg  = g_kh + (size_t)bh * Tc * HDc;
    const __half* Vtg = g_vt + (size_t)bh * HDc * Tc;
    __half*       Og  = g_ch + (size_t)bh * Tc * HDc;

    __half* Ps = fsm + HPS;
    const uint32_t psb = sb + HPS * 2u;

    // Q fragments (pre-scaled by CSC at projection), held all loop
    uint32_t qf[8][4];
    {
        const int r0 = qb + wq + g, r1 = r0 + 8;
#pragma unroll
        for (int ds = 0; ds < 8; ds++) {
            qf[ds][0] = *(const uint32_t*)&Qg[(size_t)r0 * HDc + ds * 16 + 2 * t];
            qf[ds][1] = *(const uint32_t*)&Qg[(size_t)r1 * HDc + ds * 16 + 2 * t];
            qf[ds][2] = *(const uint32_t*)&Qg[(size_t)r0 * HDc + ds * 16 + 8 + 2 * t];
            qf[ds][3] = *(const uint32_t*)&Qg[(size_t)r1 * HDc + ds * 16 + 8 + 2 * t];
        }
    }

    float o[16][4];
#pragma unroll
    for (int nt = 0; nt < 16; nt++)
#pragma unroll
        for (int j = 0; j < 4; j++) o[nt][j] = 0.f;

    float m0 = -1e30f, m1 = -1e30f, l0 = 0.f, l1 = 0.f;
    const int ktmax = qt;

    auto issue_kv = [&](int buf, int kt) {
        const int kb = kt * 64;
        const uint32_t kd = sb + (buf ? HK1 : HK0) * 2u;
        const uint32_t vd = sb + (buf ? HV1 : HV0) * 2u;
#pragma unroll
        for (int it = 0; it < 8; it++) {
            const int idx = tid + it * 128;          // 0..1023
            const int c = idx >> 4, s = idx & 15;
            cp16(kd + (uint32_t)(c * 136 + s * 8) * 2u,
                 Kg + (size_t)(kb + c) * HDc + s * 8);
        }
#pragma unroll
        for (int it = 0; it < 8; it++) {
            const int idx = tid + it * 128;          // 0..1023
            const int d = idx >> 3, s = idx & 7;
            cp16(vd + (uint32_t)(d * 72 + s * 8) * 2u,
                 Vtg + (size_t)d * Tc + kb + s * 8);
        }
        CP_COMMIT();
    };

    issue_kv(0, 0);

    for (int kt = 0; kt <= ktmax; kt++) {
        const int cur = kt & 1;
        CP_WAIT0();
        __syncthreads();
        if (kt < ktmax) issue_kv(1 - cur, kt + 1);

        const uint32_t ks_b = sb + (cur ? HK1 : HK0) * 2u;
        const uint32_t vs_b = sb + (cur ? HV1 : HV0) * 2u;
        const int kb = kt * 64;

        // S = Q K^T : warp 16q x 64c
        float s[8][4];
#pragma unroll
        for (int nt = 0; nt < 8; nt++)
#pragma unroll
            for (int j = 0; j < 4; j++) s[nt][j] = 0.f;

#pragma unroll
        for (int ds = 0; ds < 8; ds++) {
#pragma unroll
            for (int j = 0; j < 4; j++) {
                uint32_t br[4];
                ldm4(ks_b + (uint32_t)(((2 * j + b_rgrp) * 8 + b_row) * 136
                                       + ds * 16 + b_col8) * 2u, br);
                mma16(s[2 * j],     qf[ds], br[0], br[1]);
                mma16(s[2 * j + 1], qf[ds], br[2], br[3]);
            }
        }

        // causal mask (diagonal tile only); scale already folded into Q
        const int qr0 = qb + wq + g, qr1 = qr0 + 8;
        if (kt == qt) {
#pragma unroll
            for (int nt = 0; nt < 8; nt++) {
                const int c0 = kb + nt * 8 + 2 * t;
                if (c0     > qr0) s[nt][0] = -1e30f;
                if (c0 + 1 > qr0) s[nt][1] = -1e30f;
                if (c0     > qr1) s[nt][2] = -1e30f;
                if (c0 + 1 > qr1) s[nt][3] = -1e30f;
            }
        }

        // online softmax (log2 domain)
        float mx0 = -1e30f, mx1 = -1e30f;
#pragma unroll
        for (int nt = 0; nt < 8; nt++) {
            mx0 = fmaxf(mx0, fmaxf(s[nt][0], s[nt][1]));
            mx1 = fmaxf(mx1, fmaxf(s[nt][2], s[nt][3]));
        }
        mx0 = fmaxf(mx0, __shfl_xor_sync(0xffffffffu, mx0, 1));
        mx0 = fmaxf(mx0, __shfl_xor_sync(0xffffffffu, mx0, 2));
        mx1 = fmaxf(mx1, __shfl_xor_sync(0xffffffffu, mx1, 1));
        mx1 = fmaxf(mx1, __shfl_xor_sync(0xffffffffu, mx1, 2));

        const float mn0 = fmaxf(m0, mx0), mn1 = fmaxf(m1, mx1);
        const float a0 = ex2(m0 - mn0), a1 = ex2(m1 - mn1);

        float ls0 = 0.f, ls1 = 0.f;
#pragma unroll
        for (int nt = 0; nt < 8; nt++) {
            const float p0 = ex2(s[nt][0] - mn0);
            const float p1 = ex2(s[nt][1] - mn0);
            const float p2 = ex2(s[nt][2] - mn1);
            const float p3 = ex2(s[nt][3] - mn1);
            ls0 += p0 + p1; ls1 += p2 + p3;
            *(uint32_t*)&Ps[(wq + g) * 72 + nt * 8 + 2 * t]     = h2u(p0, p1);
            *(uint32_t*)&Ps[(wq + g + 8) * 72 + nt * 8 + 2 * t] = h2u(p2, p3);
        }
        ls0 += __shfl_xor_sync(0xffffffffu, ls0, 1);
        ls0 += __shfl_xor_sync(0xffffffffu, ls0, 2);
        ls1 += __shfl_xor_sync(0xffffffffu, ls1, 1);
        ls1 += __shfl_xor_sync(0xffffffffu, ls1, 2);
        l0 = l0 * a0 + ls0;
        l1 = l1 * a1 + ls1;
        m0 = mn0; m1 = mn1;

#pragma unroll
        for (int nt = 0; nt < 16; nt++) {
            o[nt][0] *= a0; o[nt][1] *= a0;
            o[nt][2] *= a1; o[nt][3] *= a1;
        }
        __syncwarp();    // Ps stores (cross-lane) visible to ldmatrix

        // O += P V : warp 16q x 128d
#pragma unroll
        for (int ks = 0; ks < 4; ks++) {
            uint32_t pa[4];
            ldm4(psb + (uint32_t)((wq + a_row) * 72 + ks * 16 + a_col8) * 2u,
                 pa);
#pragma unroll
            for (int j = 0; j < 8; j++) {
                uint32_t vb[4];
                ldm4(vs_b + (uint32_t)(((2 * j + b_rgrp) * 8 + b_row) * 72
                                       + ks * 16 + b_col8) * 2u, vb);
                mma16(o[2 * j],     pa, vb[0], vb[1]);
                mma16(o[2 * j + 1], pa, vb[2], vb[3]);
            }
        }
    }

    // epilogue
    const float il0 = 1.f / l0, il1 = 1.f / l1;
    const int r0 = qb + wq + g, r1 = r0 + 8;
#pragma unroll
    for (int nt = 0; nt < 16; nt++) {
        const int c = nt * 8 + 2 * t;
        *(uint32_t*)&Og[(size_t)r0 * HDc + c] = h2u(o[nt][0] * il0, o[nt][1] * il0);
        *(uint32_t*)&Og[(size_t)r1 * HDc + c] = h2u(o[nt][2] * il1, o[nt][3] * il1);
    }
}

// ---------------------------------------------------------------------------
extern "C" void kernel_launch(void* const* d_in, const int* in_sizes, int n_in,
                              void* d_out, int out_size)
{
    const float* x  = (const float*)d_in[0];
    const float* y  = (const float*)d_in[1];
    const float* Wq = (const float*)d_in[2];
    const float* bq = (const float*)d_in[3];
    const float* Wk = (const float*)d_in[4];
    const float* bk = (const float*)d_in[5];
    const float* Wv = (const float*)d_in[6];
    const float* bv = (const float*)d_in[7];
    const float* Wo = (const float*)d_in[8];
    const float* bo = (const float*)d_in[9];
    float* out = (float*)d_out;

    cudaFuncSetAttribute(flash_attn,
                         cudaFuncAttributeMaxDynamicSharedMemorySize, FLASH_SMEM);
    cudaFuncSetAttribute(gemm_qkv,
                         cudaFuncAttributeMaxDynamicSharedMemorySize, GEMM_SMEM);
    cudaFuncSetAttribute(gemm_out,
                         cudaFuncAttributeMaxDynamicSharedMemorySize, GEMM_SMEM);

    __half* gx; cudaGetSymbolAddress((void**)&gx, g_xh);
    __half* gy; cudaGetSymbolAddress((void**)&gy, g_yh);
    __half* gw; cudaGetSymbolAddress((void**)&gw, g_wh);
    __half* gq; cudaGetSymbolAddress((void**)&gq, g_qh);
    __half* gk; cudaGetSymbolAddress((void**)&gk, g_kh);
    __half* gvt; cudaGetSymbolAddress((void**)&gvt, g_vt);
    __half* gc; cudaGetSymbolAddress((void**)&gc, g_ch);

    // 1. convert inputs + weights to fp16 (round-12 two launches)
    const int nXY4 = (Mc * Dc) / 4;
    const int nW4  = (Dc * Dc) / 4;
    conv_h2<<<dim3((nXY4 + 255)/256, 2), 256>>>(
        (const float4*)x, (uint2*)gx, (const float4*)y, (uint2*)gy, nXY4);
    conv_h4<<<dim3((nW4 + 255)/256, 4), 256>>>(
        (const float4*)Wq, (const float4*)Wk, (const float4*)Wv,
        (const float4*)Wo, (uint2*)gw, nW4);

    // 2. fused Q/K/V projections (single launch, 1536 CTAs)
    dim3 gblk(256);
    dim3 qkvgrid(Dc/128, Mc/128, 3);   // (8, 64, 3)
    gemm_qkv<<<qkvgrid, gblk, GEMM_SMEM>>>(gx, gy, gw, bq, bk, bv,
                                           gq, gk, gvt);

    // 3. attention
    dim3 fgrid(Tc/64, Bc*Hc);     // (32, 32) = 1024 CTAs
    flash_attn<<<fgrid, dim3(128), FLASH_SMEM>>>();

    // 4. output projection (round-12 BM=128, 512 CTAs)
    dim3 ogrid(Dc/128, Mc/128);   // (8, 64)
    gemm_out<<<ogrid, gblk, GEMM_SMEM>>>(gc, gw + 3*Dc*Dc, bo, out);
}

// round 17
// speedup vs baseline: 1.7144x; 1.0214x over previous
#include <cuda_runtime.h>
#include <cuda_fp16.h>
#include <math.h>
#include <stdint.h>

#define Bc  4
#define Tc  2048
#define Dc  1024
#define Hc  8
#define HDc 128
#define Mc  (Bc*Tc)

// Scratch (fp16)
__device__ __half g_qh[Bc*Tc*Dc];           // [B,H,T,HD], pre-scaled by c*log2e
__device__ __half g_kh[Bc*Tc*Dc];           // [B,H,T,HD]
__device__ __half g_vt[Bc*Tc*Dc];           // [B,H,HD,T]  (V transposed)
__device__ __half g_ch[Bc*Tc*Dc];           // ctx [B,H,T,HD]
__device__ __half g_xh[Bc*Tc*Dc];
__device__ __half g_yh[Bc*Tc*Dc];
__device__ __half g_wh[4][Dc*Dc];

// ---------------------------------------------------------------------------
// helpers
// ---------------------------------------------------------------------------
__device__ __forceinline__ uint32_t smem_u32(const void* p) {
    uint32_t a;
    asm("{ .reg .u64 t; cvta.to.shared.u64 t, %1; cvt.u32.u64 %0, t; }"
        : "=r"(a) : "l"(p));
    return a;
}
__device__ __forceinline__ float ex2(float x) {
    float y;
    asm("ex2.approx.f32 %0, %1;" : "=f"(y) : "f"(x));
    return y;
}
__device__ __forceinline__ uint32_t h2u(float a, float b) {
    __half2 h = __floats2half2_rn(a, b);
    return *(uint32_t*)&h;
}
__device__ __forceinline__ void cp16(uint32_t dst, const void* src) {
    asm volatile("cp.async.cg.shared.global [%0], [%1], 16;" :: "r"(dst), "l"(src));
}
#define CP_COMMIT() asm volatile("cp.async.commit_group;" ::: "memory")
#define CP_WAIT1()  asm volatile("cp.async.wait_group 1;" ::: "memory")
#define CP_WAIT0()  asm volatile("cp.async.wait_group 0;" ::: "memory")

// ldmatrix x4 (b16, non-trans)
__device__ __forceinline__ void ldm4(uint32_t addr, uint32_t* r) {
    asm volatile("ldmatrix.sync.aligned.m8n8.x4.shared.b16 {%0,%1,%2,%3}, [%4];"
                 : "=r"(r[0]), "=r"(r[1]), "=r"(r[2]), "=r"(r[3]) : "r"(addr));
}

// m16n8k16 fp16 MMA, f32 accumulate in place.
__device__ __forceinline__ void mma16(float* d, const uint32_t* a,
                                      uint32_t b0, uint32_t b1) {
    asm volatile(
        "mma.sync.aligned.m16n8k16.row.col.f32.f16.f16.f32 "
        "{%0,%1,%2,%3}, {%4,%5,%6,%7}, {%8,%9}, {%0,%1,%2,%3};"
        : "+f"(d[0]), "+f"(d[1]), "+f"(d[2]), "+f"(d[3])
        : "r"(a[0]), "r"(a[1]), "r"(a[2]), "r"(a[3]), "r"(b0), "r"(b1));
}

#define CSC 0.12751743342f   // (1/sqrt(128)) * log2(e)

// ---------------------------------------------------------------------------
// fp32 -> fp16 converts (2 fused launches)
// ---------------------------------------------------------------------------
__global__ void conv_h2(const float4* __restrict__ a, uint2* __restrict__ oa,
                        const float4* __restrict__ b, uint2* __restrict__ ob,
                        int n4) {
    int i = blockIdx.x * blockDim.x + threadIdx.x;
    const float4* s = blockIdx.y ? b : a;
    uint2* d = blockIdx.y ? ob : oa;
    if (i < n4) {
        float4 v = s[i];
        uint2 o;
        o.x = h2u(v.x, v.y);
        o.y = h2u(v.z, v.w);
        d[i] = o;
    }
}

__global__ void conv_h4(const float4* __restrict__ w0, const float4* __restrict__ w1,
                        const float4* __restrict__ w2, const float4* __restrict__ w3,
                        uint2* __restrict__ o0, int n4) {
    int i = blockIdx.x * blockDim.x + threadIdx.x;
    const float4* s = (blockIdx.y == 0) ? w0 : (blockIdx.y == 1) ? w1
                      : (blockIdx.y == 2) ? w2 : w3;
    uint2* d = o0 + (size_t)blockIdx.y * (Dc * Dc / 4);
    if (i < n4) {
        float4 v = s[i];
        uint2 o;
        o.x = h2u(v.x, v.y);
        o.y = h2u(v.z, v.w);
        d[i] = o;
    }
}

// ---------------------------------------------------------------------------
// Fused Q/K/V projection GEMM (blockIdx.z selects problem).
// z=0: Q = (x Wq^T + bq)*CSC -> g_qh   (scale folded for flash)
// z=1: K = y Wk^T + bk       -> g_kh
// z=2: V = y Wv^T + bv       -> g_vt (V^T layout, smem-staged transpose)
// ---------------------------------------------------------------------------
#define GEMM_SMEM (3*20480)

__global__ __launch_bounds__(256, 2)
void gemm_qkv(const __half* __restrict__ Ax, const __half* __restrict__ Ay,
              const __half* __restrict__ gw,
              const float* __restrict__ bq, const float* __restrict__ bk,
              const float* __restrict__ bv,
              __half* __restrict__ gq, __half* __restrict__ gk,
              __half* __restrict__ gvt)
{
    extern __shared__ __align__(16) char smemc[];
    const uint32_t sb = smem_u32(smemc);

    const int z = blockIdx.z;
    const __half* A    = (z == 0) ? Ax : Ay;
    const __half* Wg   = gw + (size_t)z * Dc * Dc;
    const float*  bias = (z == 0) ? bq : (z == 1) ? bk : bv;
    __half*       outh = (z == 0) ? gq : (z == 1) ? gk : gvt;
    const float   osc  = (z == 0) ? CSC : 1.0f;

    const int tid = threadIdx.x;
    const int wid = tid >> 5, lane = tid & 31;
    const int g = lane >> 2, t = lane & 3;
    const int wm = (wid & 3) * 32, wn = (wid >> 2) * 64;
    const int bn = blockIdx.x * 128, bm = blockIdx.y * 128;

    const int a_row = lane & 15, a_col8 = ((lane >> 4) & 1) * 8;
    const int b_rgrp = (lane >> 4) & 1, b_row = lane & 7;
    const int b_col8 = ((lane >> 3) & 1) * 8;

    auto issue = [&](int stg, int k0) {
        const uint32_t da = sb + (uint32_t)(stg * 20480);
        const uint32_t db = da + 10240u;
#pragma unroll
        for (int it = 0; it < 2; it++) {
            const int idx = tid + it * 256;          // 0..511
            const int row = idx >> 2, s = idx & 3;
            cp16(da + (uint32_t)(row * 40 + s * 8) * 2u,
                 A + (size_t)(bm + row) * Dc + k0 + s * 8);
        }
#pragma unroll
        for (int it = 0; it < 2; it++) {
            const int idx = tid + it * 256;
            const int row = idx >> 2, s = idx & 3;
            cp16(db + (uint32_t)(row * 40 + s * 8) * 2u,
                 Wg + (size_t)(bn + row) * Dc + k0 + s * 8);
        }
        CP_COMMIT();
    };

    float c[2][8][4];
#pragma unroll
    for (int mt = 0; mt < 2; mt++)
#pragma unroll
        for (int nt = 0; nt < 8; nt++)
#pragma unroll
            for (int j = 0; j < 4; j++) c[mt][nt][j] = 0.f;

    issue(0, 0); issue(1, 32);

    for (int i = 0; i < 32; i++) {
        if (i == 31) { CP_WAIT0(); } else { CP_WAIT1(); }
        __syncthreads();
        if (i + 2 < 32) issue((i + 2) % 3, (i + 2) * 32);

        const uint32_t as = sb + (uint32_t)((i % 3) * 20480);
        const uint32_t bs = as + 10240u;

#pragma unroll
        for (int ks = 0; ks < 2; ks++) {
            const int kk = ks * 16;
            uint32_t a[2][4];
#pragma unroll
            for (int mt = 0; mt < 2; mt++)
                ldm4(as + (uint32_t)((wm + mt * 16 + a_row) * 40 + kk + a_col8) * 2u,
                     a[mt]);
#pragma unroll
            for (int j = 0; j < 4; j++) {
                uint32_t br[4];
                ldm4(bs + (uint32_t)((wn + (2 * j + b_rgrp) * 8 + b_row) * 40
                                     + kk + b_col8) * 2u, br);
#pragma unroll
                for (int mt = 0; mt < 2; mt++) {
                    mma16(c[mt][2 * j],     a[mt], br[0], br[1]);
                    mma16(c[mt][2 * j + 1], a[mt], br[2], br[3]);
                }
            }
        }
    }
    __syncthreads();   // protect smem reuse by z==2 epilogue staging

    const int b0i_base = bm >> 11, t0 = bm & 2047;
    const int h = bn >> 7;

    if (z == 2) {
        __half* Ts = (__half*)smemc;          // [128 n][136] halves
#pragma unroll
        for (int mt = 0; mt < 2; mt++) {
            const int r0l = wm + mt * 16 + g, r1l = r0l + 8;
#pragma unroll
            for (int nt = 0; nt < 8; nt++) {
                const int cl = wn + nt * 8 + 2 * t;
                const float bx = __ldg(bias + bn + cl);
                const float by = __ldg(bias + bn + cl + 1);
                Ts[(cl    ) * 136 + r0l] = __float2half_rn(c[mt][nt][0] + bx);
                Ts[(cl + 1) * 136 + r0l] = __float2half_rn(c[mt][nt][1] + by);
                Ts[(cl    ) * 136 + r1l] = __float2half_rn(c[mt][nt][2] + bx);
                Ts[(cl + 1) * 136 + r1l] = __float2half_rn(c[mt][nt][3] + by);
            }
        }
        __syncthreads();
#pragma unroll
        for (int it = 0; it < 8; it++) {
            const int idx = tid + it * 256;          // 0..2047
            const int row = idx >> 4, s = idx & 15;
            const uint4 v = *(const uint4*)&Ts[row * 136 + s * 8];
            *(uint4*)&outh[(((size_t)(b0i_base * Hc + h) * HDc + row)
                            * Tc) + t0 + s * 8] = v;
        }
        return;
    }

#pragma unroll
    for (int mt = 0; mt < 2; mt++) {
        const int r0 = bm + wm + mt * 16 + g;
        const int r1 = r0 + 8;
#pragma unroll
        for (int nt = 0; nt < 8; nt++) {
            const int cl = wn + nt * 8 + 2 * t;
            const int col = bn + cl;
            const float bx = __ldg(bias + col), by = __ldg(bias + col + 1);
            const float v00 = (c[mt][nt][0] + bx) * osc;
            const float v01 = (c[mt][nt][1] + by) * osc;
            const float v10 = (c[mt][nt][2] + bx) * osc;
            const float v11 = (c[mt][nt][3] + by) * osc;
            const int b0i = r0 >> 11, t0i = r0 & 2047;
            const int b1i = r1 >> 11, t1i = r1 & 2047;
            *(uint32_t*)&outh[(((size_t)(b0i * Hc + h) * Tc + t0i) * HDc) + cl]
                = h2u(v00, v01);
            *(uint32_t*)&outh[(((size_t)(b1i * Hc + h) * Tc + t1i) * HDc) + cl]
                = h2u(v10, v11);
        }
    }
}

// ---------------------------------------------------------------------------
// Output projection GEMM (BM=128, 256 thr, 2 CTAs/SM): out = ctx Wo^T + bo
// ---------------------------------------------------------------------------
__global__ __launch_bounds__(256, 2)
void gemm_out(const __half* __restrict__ A, const __half* __restrict__ Wg,
              const float* __restrict__ bias, float* __restrict__ outf)
{
    extern __shared__ __align__(16) char smemc[];
    const uint32_t sb = smem_u32(smemc);

    const int tid = threadIdx.x;
    const int wid = tid >> 5, lane = tid & 31;
    const int g = lane >> 2, t = lane & 3;
    const int wm = (wid & 3) * 32, wn = (wid >> 2) * 64;
    const int bn = blockIdx.x * 128, bm = blockIdx.y * 128;

    const int a_row = lane & 15, a_col8 = ((lane >> 4) & 1) * 8;
    const int b_rgrp = (lane >> 4) & 1, b_row = lane & 7;
    const int b_col8 = ((lane >> 3) & 1) * 8;

    auto issue = [&](int stg, int k0) {
        const uint32_t da = sb + (uint32_t)(stg * 20480);
        const uint32_t db = da + 10240u;
#pragma unroll
        for (int it = 0; it < 2; it++) {
            const int idx = tid + it * 256;
            const int row = idx >> 2, s = idx & 3;
            const int m = bm + row, b = m >> 11, tt = m & 2047;
            const int kg = k0 + s * 8;
            const int h = kg >> 7, d = kg & 127;
            cp16(da + (uint32_t)(row * 40 + s * 8) * 2u,
                 A + (((size_t)(b * Hc + h) * Tc + tt) * HDc + d));
        }
#pragma unroll
        for (int it = 0; it < 2; it++) {
            const int idx = tid + it * 256;
            const int row = idx >> 2, s = idx & 3;
            cp16(db + (uint32_t)(row * 40 + s * 8) * 2u,
                 Wg + (size_t)(bn + row) * Dc + k0 + s * 8);
        }
        CP_COMMIT();
    };

    float c[2][8][4];
#pragma unroll
    for (int mt = 0; mt < 2; mt++)
#pragma unroll
        for (int nt = 0; nt < 8; nt++)
#pragma unroll
            for (int j = 0; j < 4; j++) c[mt][nt][j] = 0.f;

    issue(0, 0); issue(1, 32);

    for (int i = 0; i < 32; i++) {
        if (i == 31) { CP_WAIT0(); } else { CP_WAIT1(); }
        __syncthreads();
        if (i + 2 < 32) issue((i + 2) % 3, (i + 2) * 32);

        const uint32_t as = sb + (uint32_t)((i % 3) * 20480);
        const uint32_t bs = as + 10240u;

#pragma unroll
        for (int ks = 0; ks < 2; ks++) {
            const int kk = ks * 16;
            uint32_t a[2][4];
#pragma unroll
            for (int mt = 0; mt < 2; mt++)
                ldm4(as + (uint32_t)((wm + mt * 16 + a_row) * 40 + kk + a_col8) * 2u,
                     a[mt]);
#pragma unroll
            for (int j = 0; j < 4; j++) {
                uint32_t br[4];
                ldm4(bs + (uint32_t)((wn + (2 * j + b_rgrp) * 8 + b_row) * 40
                                     + kk + b_col8) * 2u, br);
#pragma unroll
                for (int mt = 0; mt < 2; mt++) {
                    mma16(c[mt][2 * j],     a[mt], br[0], br[1]);
                    mma16(c[mt][2 * j + 1], a[mt], br[2], br[3]);
                }
            }
        }
    }

#pragma unroll
    for (int mt = 0; mt < 2; mt++) {
        const int r0 = bm + wm + mt * 16 + g;
        const int r1 = r0 + 8;
#pragma unroll
        for (int nt = 0; nt < 8; nt++) {
            const int cl = wn + nt * 8 + 2 * t;
            const int col = bn + cl;
            const float bx = __ldg(bias + col), by = __ldg(bias + col + 1);
            *(float2*)&outf[(size_t)r0 * Dc + col]
                = make_float2(c[mt][nt][0] + bx, c[mt][nt][1] + by);
            *(float2*)&outf[(size_t)r1 * Dc + col]
                = make_float2(c[mt][nt][2] + bx, c[mt][nt][3] + by);
        }
    }
}

// ---------------------------------------------------------------------------
// Flash attention fp16: round-16 structure, but P kept in registers
// (C-frag of S == A-frag of PV). smem size UNCHANGED (80896B) -> 2 CTAs/SM.
// ---------------------------------------------------------------------------
#define FLASH_SMEM 80896
#define HK0  0
#define HK1  8704
#define HV0  17408
#define HV1  26624

__global__ __launch_bounds__(128, 2)
void flash_attn()
{
    extern __shared__ __align__(16) __half fsm[];
    const uint32_t sb = smem_u32(fsm);

    const int bh  = blockIdx.y;
    const int qt  = gridDim.x - 1 - blockIdx.x;    // longest blocks first
    const int qb  = qt * 64;
    const int tid = threadIdx.x;
    const int wid = tid >> 5, lane = tid & 31;
    const int g = lane >> 2, t = lane & 3;
    const int wq = wid * 16;

    const int b_rgrp = (lane >> 4) & 1, b_row = lane & 7;
    const int b_col8 = ((lane >> 3) & 1) * 8;

    const __half* Qg  = g_qh + (size_t)bh * Tc * HDc;
    const __half* Kg  = g_kh + (size_t)bh * Tc * HDc;
    const __half* Vtg = g_vt + (size_t)bh * HDc * Tc;
    __half*       Og  = g_ch + (size_t)bh * Tc * HDc;

    // Q fragments (pre-scaled by CSC at projection), held all loop
    uint32_t qf[8][4];
    {
        const int r0 = qb + wq + g, r1 = r0 + 8;
#pragma unroll
        for (int ds = 0; ds < 8; ds++) {
            qf[ds][0] = *(const uint32_t*)&Qg[(size_t)r0 * HDc + ds * 16 + 2 * t];
            qf[ds][1] = *(const uint32_t*)&Qg[(size_t)r1 * HDc + ds * 16 + 2 * t];
            qf[ds][2] = *(const uint32_t*)&Qg[(size_t)r0 * HDc + ds * 16 + 8 + 2 * t];
            qf[ds][3] = *(const uint32_t*)&Qg[(size_t)r1 * HDc + ds * 16 + 8 + 2 * t];
        }
    }

    float o[16][4];
#pragma unroll
    for (int nt = 0; nt < 16; nt++)
#pragma unroll
        for (int j = 0; j < 4; j++) o[nt][j] = 0.f;

    float m0 = -1e30f, m1 = -1e30f, l0 = 0.f, l1 = 0.f;
    const int ktmax = qt;

    auto issue_kv = [&](int buf, int kt) {
        const int kb = kt * 64;
        const uint32_t kd = sb + (buf ? HK1 : HK0) * 2u;
        const uint32_t vd = sb + (buf ? HV1 : HV0) * 2u;
#pragma unroll
        for (int it = 0; it < 8; it++) {
            const int idx = tid + it * 128;          // 0..1023
            const int c = idx >> 4, s = idx & 15;
            cp16(kd + (uint32_t)(c * 136 + s * 8) * 2u,
                 Kg + (size_t)(kb + c) * HDc + s * 8);
        }
#pragma unroll
        for (int it = 0; it < 8; it++) {
            const int idx = tid + it * 128;          // 0..1023
            const int d = idx >> 3, s = idx & 7;
            cp16(vd + (uint32_t)(d * 72 + s * 8) * 2u,
                 Vtg + (size_t)d * Tc + kb + s * 8);
        }
        CP_COMMIT();
    };

    issue_kv(0, 0);

    for (int kt = 0; kt <= ktmax; kt++) {
        const int cur = kt & 1;
        CP_WAIT0();
        __syncthreads();
        if (kt < ktmax) issue_kv(1 - cur, kt + 1);

        const uint32_t ks_b = sb + (cur ? HK1 : HK0) * 2u;
        const uint32_t vs_b = sb + (cur ? HV1 : HV0) * 2u;
        const int kb = kt * 64;

        // S = Q K^T : warp 16q x 64c
        float s[8][4];
#pragma unroll
        for (int nt = 0; nt < 8; nt++)
#pragma unroll
            for (int j = 0; j < 4; j++) s[nt][j] = 0.f;

#pragma unroll
        for (int ds = 0; ds < 8; ds++) {
#pragma unroll
            for (int j = 0; j < 4; j++) {
                uint32_t br[4];
                ldm4(ks_b + (uint32_t)(((2 * j + b_rgrp) * 8 + b_row) * 136
                                       + ds * 16 + b_col8) * 2u, br);
                mma16(s[2 * j],     qf[ds], br[0], br[1]);
                mma16(s[2 * j + 1], qf[ds], br[2], br[3]);
            }
        }

        // causal mask (diagonal tile only); scale already folded into Q
        const int qr0 = qb + wq + g, qr1 = qr0 + 8;
        if (kt == qt) {
#pragma unroll
            for (int nt = 0; nt < 8; nt++) {
                const int c0 = kb + nt * 8 + 2 * t;
                if (c0     > qr0) s[nt][0] = -1e30f;
                if (c0 + 1 > qr0) s[nt][1] = -1e30f;
                if (c0     > qr1) s[nt][2] = -1e30f;
                if (c0 + 1 > qr1) s[nt][3] = -1e30f;
            }
        }

        // online softmax (log2 domain)
        float mx0 = -1e30f, mx1 = -1e30f;
#pragma unroll
        for (int nt = 0; nt < 8; nt++) {
            mx0 = fmaxf(mx0, fmaxf(s[nt][0], s[nt][1]));
            mx1 = fmaxf(mx1, fmaxf(s[nt][2], s[nt][3]));
        }
        mx0 = fmaxf(mx0, __shfl_xor_sync(0xffffffffu, mx0, 1));
        mx0 = fmaxf(mx0, __shfl_xor_sync(0xffffffffu, mx0, 2));
        mx1 = fmaxf(mx1, __shfl_xor_sync(0xffffffffu, mx1, 1));
        mx1 = fmaxf(mx1, __shfl_xor_sync(0xffffffffu, mx1, 2));

        const float mn0 = fmaxf(m0, mx0), mn1 = fmaxf(m1, mx1);
        const float a0 = ex2(m0 - mn0), a1 = ex2(m1 - mn1);

        // P fragments packed directly in registers:
        // pk[nt][0] = {P[g][8nt+2t], P[g][8nt+2t+1]}       (rows 0..15 of warp)
        // pk[nt][1] = {P[g+8][8nt+2t], P[g+8][8nt+2t+1]}
        uint32_t pk[8][2];
        float ls0 = 0.f, ls1 = 0.f;
#pragma unroll
        for (int nt = 0; nt < 8; nt++) {
            const float p0 = ex2(s[nt][0] - mn0);
            const float p1 = ex2(s[nt][1] - mn0);
            const float p2 = ex2(s[nt][2] - mn1);
            const float p3 = ex2(s[nt][3] - mn1);
            ls0 += p0 + p1; ls1 += p2 + p3;
            pk[nt][0] = h2u(p0, p1);
            pk[nt][1] = h2u(p2, p3);
        }
        ls0 += __shfl_xor_sync(0xffffffffu, ls0, 1);
        ls0 += __shfl_xor_sync(0xffffffffu, ls0, 2);
        ls1 += __shfl_xor_sync(0xffffffffu, ls1, 1);
        ls1 += __shfl_xor_sync(0xffffffffu, ls1, 2);
        l0 = l0 * a0 + ls0;
        l1 = l1 * a1 + ls1;
        m0 = mn0; m1 = mn1;

#pragma unroll
        for (int nt = 0; nt < 16; nt++) {
            o[nt][0] *= a0; o[nt][1] *= a0;
            o[nt][2] *= a1; o[nt][3] *= a1;
        }

        // O += P V : warp 16q x 128d ; P A-fragments straight from pk
#pragma unroll
        for (int ks = 0; ks < 4; ks++) {
            uint32_t pa[4];
            pa[0] = pk[2 * ks][0];
            pa[1] = pk[2 * ks][1];
            pa[2] = pk[2 * ks + 1][0];
            pa[3] = pk[2 * ks + 1][1];
#pragma unroll
            for (int j = 0; j < 8; j++) {
                uint32_t vb[4];
                ldm4(vs_b + (uint32_t)(((2 * j + b_rgrp) * 8 + b_row) * 72
                                       + ks * 16 + b_col8) * 2u, vb);
                mma16(o[2 * j],     pa, vb[0], vb[1]);
                mma16(o[2 * j + 1], pa, vb[2], vb[3]);
            }
        }
    }

    // epilogue
    const float il0 = 1.f / l0, il1 = 1.f / l1;
    const int r0 = qb + wq + g, r1 = r0 + 8;
#pragma unroll
    for (int nt = 0; nt < 16; nt++) {
        const int c = nt * 8 + 2 * t;
        *(uint32_t*)&Og[(size_t)r0 * HDc + c] = h2u(o[nt][0] * il0, o[nt][1] * il0);
        *(uint32_t*)&Og[(size_t)r1 * HDc + c] = h2u(o[nt][2] * il1, o[nt][3] * il1);
    }
}

// ---------------------------------------------------------------------------
extern "C" void kernel_launch(void* const* d_in, const int* in_sizes, int n_in,
                              void* d_out, int out_size)
{
    const float* x  = (const float*)d_in[0];
    const float* y  = (const float*)d_in[1];
    const float* Wq = (const float*)d_in[2];
    const float* bq = (const float*)d_in[3];
    const float* Wk = (const float*)d_in[4];
    const float* bk = (const float*)d_in[5];
    const float* Wv = (const float*)d_in[6];
    const float* bv = (const float*)d_in[7];
    const float* Wo = (const float*)d_in[8];
    const float* bo = (const float*)d_in[9];
    float* out = (float*)d_out;

    cudaFuncSetAttribute(flash_attn,
                         cudaFuncAttributeMaxDynamicSharedMemorySize, FLASH_SMEM);
    cudaFuncSetAttribute(gemm_qkv,
                         cudaFuncAttributeMaxDynamicSharedMemorySize, GEMM_SMEM);
    cudaFuncSetAttribute(gemm_out,
                         cudaFuncAttributeMaxDynamicSharedMemorySize, GEMM_SMEM);

    __half* gx; cudaGetSymbolAddress((void**)&gx, g_xh);
    __half* gy; cudaGetSymbolAddress((void**)&gy, g_yh);
    __half* gw; cudaGetSymbolAddress((void**)&gw, g_wh);
    __half* gq; cudaGetSymbolAddress((void**)&gq, g_qh);
    __half* gk; cudaGetSymbolAddress((void**)&gk, g_kh);
    __half* gvt; cudaGetSymbolAddress((void**)&gvt, g_vt);
    __half* gc; cudaGetSymbolAddress((void**)&gc, g_ch);

    // 1. convert inputs + weights to fp16
    const int nXY4 = (Mc * Dc) / 4;
    const int nW4  = (Dc * Dc) / 4;
    conv_h2<<<dim3((nXY4 + 255)/256, 2), 256>>>(
        (const float4*)x, (uint2*)gx, (const float4*)y, (uint2*)gy, nXY4);
    conv_h4<<<dim3((nW4 + 255)/256, 4), 256>>>(
        (const float4*)Wq, (const float4*)Wk, (const float4*)Wv,
        (const float4*)Wo, (uint2*)gw, nW4);

    // 2. fused Q/K/V projections (single launch, 1536 CTAs)
    dim3 gblk(256);
    dim3 qkvgrid(Dc/128, Mc/128, 3);   // (8, 64, 3)
    gemm_qkv<<<qkvgrid, gblk, GEMM_SMEM>>>(gx, gy, gw, bq, bk, bv,
                                           gq, gk, gvt);

    // 3. attention
    dim3 fgrid(Tc/64, Bc*Hc);     // (32, 32) = 1024 CTAs
    flash_attn<<<fgrid, dim3(128), FLASH_SMEM>>>();

    // 4. output projection (BM=128, 512 CTAs)
    dim3 ogrid(Dc/128, Mc/128);   // (8, 64)
    gemm_out<<<ogrid, gblk, GEMM_SMEM>>>(gc, gw + 3*Dc*Dc, bo, out);
}